// round 4
// baseline (speedup 1.0000x reference)
#include <cuda_runtime.h>
#include <math.h>

#define NN    8192
#define KDIM  256
#define CDIM  256     // HEADS*OUT_DIM
#define FDIM  128
#define NHEAD 2

#define BM 32
#define BN 32

// ---- scratch (device globals; no allocation allowed) ----
__device__ float g_T[NN * CDIM];      // transformed features [N][2*128]
__device__ float g_Agg[NN * CDIM];    // per-head normalized aggregation
__device__ float g_S[NN * NHEAD];     // src scores
__device__ float g_D[NN * NHEAD];     // dst scores
__device__ float g_Es[NN * NHEAD];    // exp(s)
__device__ float g_Fs[NN * NHEAD];    // exp(0.2 s)
__device__ float g_Ed[NN * NHEAD];    // exp(d)
__device__ float g_Fd[NN * NHEAD];    // exp(0.2 d)

// ============================================================
// Kernel 1: T = features @ W^T   (8192x256 @ 256x256^T)
// 64x64 tile, BK=32, 256 threads, 4x4 micro-tile
// FIX (R4): loader now fills all 64 rows of Asm/Bsm (2 float4 per thread);
// previous version only wrote rows 0..31 -> garbage in rows 32..63.
// ============================================================
__global__ void __launch_bounds__(256) k_transform(const float* __restrict__ feat,
                                                   const float* __restrict__ W) {
    __shared__ float Asm[32][64];   // [k][row]
    __shared__ float Bsm[32][64];   // [k][col]
    int i0 = blockIdx.x * 64;
    int c0 = blockIdx.y * 64;
    int t = threadIdx.x;
    int tr = t & 15, tc = t >> 4;

    float acc[4][4];
#pragma unroll
    for (int a = 0; a < 4; a++)
#pragma unroll
        for (int b = 0; b < 4; b++) acc[a][b] = 0.f;

    int lrow = t >> 3, lkg = t & 7;   // lrow 0..31, lkg 0..7 (4 k each)
    for (int k0 = 0; k0 < KDIM; k0 += 32) {
        float4 va0 = *(const float4*)&feat[(i0 + lrow) * KDIM + k0 + lkg * 4];
        float4 va1 = *(const float4*)&feat[(i0 + lrow + 32) * KDIM + k0 + lkg * 4];
        float4 vb0 = *(const float4*)&W[(c0 + lrow) * KDIM + k0 + lkg * 4];
        float4 vb1 = *(const float4*)&W[(c0 + lrow + 32) * KDIM + k0 + lkg * 4];
        __syncthreads();
        Asm[lkg * 4 + 0][lrow]      = va0.x; Asm[lkg * 4 + 1][lrow]      = va0.y;
        Asm[lkg * 4 + 2][lrow]      = va0.z; Asm[lkg * 4 + 3][lrow]      = va0.w;
        Asm[lkg * 4 + 0][lrow + 32] = va1.x; Asm[lkg * 4 + 1][lrow + 32] = va1.y;
        Asm[lkg * 4 + 2][lrow + 32] = va1.z; Asm[lkg * 4 + 3][lrow + 32] = va1.w;
        Bsm[lkg * 4 + 0][lrow]      = vb0.x; Bsm[lkg * 4 + 1][lrow]      = vb0.y;
        Bsm[lkg * 4 + 2][lrow]      = vb0.z; Bsm[lkg * 4 + 3][lrow]      = vb0.w;
        Bsm[lkg * 4 + 0][lrow + 32] = vb1.x; Bsm[lkg * 4 + 1][lrow + 32] = vb1.y;
        Bsm[lkg * 4 + 2][lrow + 32] = vb1.z; Bsm[lkg * 4 + 3][lrow + 32] = vb1.w;
        __syncthreads();
#pragma unroll
        for (int kk = 0; kk < 32; kk++) {
            float4 a4 = *(const float4*)&Asm[kk][tr * 4];
            float4 b4 = *(const float4*)&Bsm[kk][tc * 4];
            float aa[4] = {a4.x, a4.y, a4.z, a4.w};
            float bb[4] = {b4.x, b4.y, b4.z, b4.w};
#pragma unroll
            for (int r = 0; r < 4; r++)
#pragma unroll
                for (int c = 0; c < 4; c++)
                    acc[r][c] = fmaf(aa[r], bb[c], acc[r][c]);
        }
    }
#pragma unroll
    for (int r = 0; r < 4; r++)
#pragma unroll
        for (int c = 0; c < 4; c++)
            g_T[(i0 + tr * 4 + r) * CDIM + c0 + tc * 4 + c] = acc[r][c];
}

// ============================================================
// Kernel 2: per-node scores + separable exp factors
// warp per row, 8 rows per CTA
// ============================================================
__global__ void __launch_bounds__(256) k_scores(const float* __restrict__ attn_src,
                                                const float* __restrict__ attn_dst) {
    __shared__ float as_[CDIM], ad_[CDIM];
    int t = threadIdx.x;
    as_[t] = attn_src[t];
    ad_[t] = attn_dst[t];
    __syncthreads();
    int warp = t >> 5, lane = t & 31;
    int row = blockIdx.x * 8 + warp;

    float s0 = 0.f, s1 = 0.f, d0 = 0.f, d1 = 0.f;
#pragma unroll
    for (int f = lane; f < FDIM; f += 32) {
        float t0 = g_T[row * CDIM + f];
        float t1 = g_T[row * CDIM + FDIM + f];
        s0 = fmaf(t0, as_[f], s0);
        d0 = fmaf(t0, ad_[f], d0);
        s1 = fmaf(t1, as_[FDIM + f], s1);
        d1 = fmaf(t1, ad_[FDIM + f], d1);
    }
#pragma unroll
    for (int o = 16; o > 0; o >>= 1) {
        s0 += __shfl_xor_sync(0xFFFFFFFFu, s0, o);
        s1 += __shfl_xor_sync(0xFFFFFFFFu, s1, o);
        d0 += __shfl_xor_sync(0xFFFFFFFFu, d0, o);
        d1 += __shfl_xor_sync(0xFFFFFFFFu, d1, o);
    }
    if (lane == 0) {
        g_S[row * 2 + 0] = s0;  g_S[row * 2 + 1] = s1;
        g_D[row * 2 + 0] = d0;  g_D[row * 2 + 1] = d1;
        g_Es[row * 2 + 0] = expf(s0);         g_Es[row * 2 + 1] = expf(s1);
        g_Fs[row * 2 + 0] = expf(0.2f * s0);  g_Fs[row * 2 + 1] = expf(0.2f * s1);
        g_Ed[row * 2 + 0] = expf(d0);         g_Ed[row * 2 + 1] = expf(d1);
        g_Fd[row * 2 + 0] = expf(0.2f * d0);  g_Fd[row * 2 + 1] = expf(0.2f * d1);
    }
}

// ============================================================
// Kernel 3: fused masked-softmax aggregation (one adjacency pass)
// CTA: BM=32 src rows; loop over dst in BN=32 tiles.
//   P phase: p = adj ? (s+d>=0 ? E_i*E_j : F_i*F_j) : 0   (separable exp)
//   FMA phase: register-tiled P[2][32][32] @ Tsm[32][256]
// ============================================================
__global__ void __launch_bounds__(256) k_aggregate(const int* __restrict__ adj) {
    __shared__ float Tsm[BN][CDIM];           // 32 KB
    __shared__ float Psm[NHEAD][BN][BM];      // 8 KB
    __shared__ float lsm[NHEAD][BM];
    __shared__ float rowS[NHEAD][BM], rowE[NHEAD][BM], rowF[NHEAD][BM];
    __shared__ float dD[NHEAD][BN], dE[NHEAD][BN], dF[NHEAD][BN];

    int i0 = blockIdx.x * BM;
    int t = threadIdx.x;

    if (t < NHEAD * BM) {
        int h = t / BM, r = t % BM;
        int gi = (i0 + r) * 2 + h;
        rowS[h][r] = g_S[gi];
        rowE[h][r] = g_Es[gi];
        rowF[h][r] = g_Fs[gi];
        lsm[h][r] = 0.f;
    }

    // producer role
    int pr = t >> 3;      // src row 0..31
    int pjq = t & 7;      // j quad 0..7
    float lp0 = 0.f, lp1 = 0.f;

    // fma role
    int fr = t & 15;      // row group: rows 2*fr, 2*fr+1
    int fc = t >> 4;      // col group: cols fc*16..fc*16+15
    int head = fc >> 3;
    float acc[2][16];
#pragma unroll
    for (int r = 0; r < 2; r++)
#pragma unroll
        for (int q = 0; q < 16; q++) acc[r][q] = 0.f;

    int4 a_cur = *(const int4*)&adj[(i0 + pr) * NN + pjq * 4];

    const int NT = NN / BN;
    for (int tile = 0; tile < NT; tile++) {
        int j0 = tile * BN;
        // load T tile (L2 resident): 2048 float4 by 256 threads
#pragma unroll
        for (int p = 0; p < 8; p++) {
            int idx = t + p * 256;
            int jr = idx >> 6;
            int cg = idx & 63;
            *(float4*)&Tsm[jr][cg * 4] = *(const float4*)&g_T[(j0 + jr) * CDIM + cg * 4];
        }
        if (t < NHEAD * BN) {
            int jj = t >> 1, h = t & 1;
            int gj = (j0 + jj) * 2 + h;
            dD[h][jj] = g_D[gj];
            dE[h][jj] = g_Ed[gj];
            dF[h][jj] = g_Fd[gj];
        }
        __syncthreads();

        // ---- P phase ----
        {
            int av[4] = {a_cur.x, a_cur.y, a_cur.z, a_cur.w};
            float sS0 = rowS[0][pr], sE0 = rowE[0][pr], sF0 = rowF[0][pr];
            float sS1 = rowS[1][pr], sE1 = rowE[1][pr], sF1 = rowF[1][pr];
#pragma unroll
            for (int q = 0; q < 4; q++) {
                int jl = pjq * 4 + q;
                float p0 = 0.f, p1 = 0.f;
                if (av[q] > 0) {
                    float c0 = sS0 + dD[0][jl];
                    p0 = (c0 >= 0.f) ? sE0 * dE[0][jl] : sF0 * dF[0][jl];
                    float c1 = sS1 + dD[1][jl];
                    p1 = (c1 >= 0.f) ? sE1 * dE[1][jl] : sF1 * dF[1][jl];
                }
                Psm[0][jl][pr] = p0;
                Psm[1][jl][pr] = p1;
                lp0 += p0;
                lp1 += p1;
            }
        }
        // prefetch next adjacency tile (hide DRAM latency behind FMA phase)
        int4 a_next = make_int4(0, 0, 0, 0);
        if (tile + 1 < NT)
            a_next = *(const int4*)&adj[(i0 + pr) * NN + j0 + BN + pjq * 4];
        __syncthreads();

        // ---- FMA phase: acc += P^T tile-slice * T tile ----
#pragma unroll 8
        for (int jj = 0; jj < BN; jj++) {
            float2 pf = *(const float2*)&Psm[head][jj][fr * 2];
            const float4* tp = (const float4*)&Tsm[jj][fc * 16];
            float bb[16];
            *(float4*)&bb[0]  = tp[0];
            *(float4*)&bb[4]  = tp[1];
            *(float4*)&bb[8]  = tp[2];
            *(float4*)&bb[12] = tp[3];
#pragma unroll
            for (int q = 0; q < 16; q++) {
                acc[0][q] = fmaf(pf.x, bb[q], acc[0][q]);
                acc[1][q] = fmaf(pf.y, bb[q], acc[1][q]);
            }
        }
        __syncthreads();
        a_cur = a_next;
    }

    atomicAdd(&lsm[0][pr], lp0);
    atomicAdd(&lsm[1][pr], lp1);
    __syncthreads();

#pragma unroll
    for (int rr = 0; rr < 2; rr++) {
        int r = fr * 2 + rr;
        float l = lsm[head][r];
        float inv = (l > 0.f) ? (1.f / l) : 0.f;   // empty rows -> 0 (nan_to_num)
        float* o = &g_Agg[(i0 + r) * CDIM + fc * 16];
#pragma unroll
        for (int q = 0; q < 16; q++) o[q] = acc[rr][q] * inv;
    }
}

// ============================================================
// Kernel 4: mean over heads
// ============================================================
__global__ void __launch_bounds__(256) k_combine(float* __restrict__ out) {
    int idx = blockIdx.x * 256 + threadIdx.x;
    int i = idx >> 7;
    int f = idx & 127;
    out[idx] = 0.5f * (g_Agg[i * CDIM + f] + g_Agg[i * CDIM + FDIM + f]);
}

// ============================================================
extern "C" void kernel_launch(void* const* d_in, const int* in_sizes, int n_in,
                              void* d_out, int out_size) {
    const float* feat = (const float*)d_in[0];
    const int*   adj  = (const int*)d_in[1];
    const float* W    = (const float*)d_in[2];
    const float* asrc = (const float*)d_in[3];
    const float* adst = (const float*)d_in[4];
    float* out = (float*)d_out;

    dim3 g1(NN / 64, CDIM / 64);
    k_transform<<<g1, 256>>>(feat, W);
    k_scores<<<NN / 8, 256>>>(asrc, adst);
    k_aggregate<<<NN / BM, 256>>>(adj);
    k_combine<<<(NN * FDIM) / 256, 256>>>(out);
}

// round 7
// speedup vs baseline: 1.6136x; 1.6136x over previous
#include <cuda_runtime.h>
#include <cstdint>
#include <math.h>

#define NN    8192
#define KDIM  256
#define CDIM  256
#define FDIM  128
#define KT    32          // dst-tile width
#define BM    64          // src rows per CTA
#define NTILE (NN / KT)   // 256

// ---- scratch (device globals) ----
__device__ float  g_T [NN * CDIM];   // transformed [i][h*128+f] (fp32)
__device__ float4 g_SRCF[NN * 2];    // {S, e^S, e^{.2S}, 0} per (node, head)
__device__ float4 g_DSTF[NN * 2];    // {D, e^D, e^{.2D}, 0} per (node, head)

__device__ __forceinline__ uint32_t f2tf32(float x) {
    uint32_t u;
    asm("cvt.rna.tf32.f32 %0, %1;" : "=r"(u) : "f"(x));
    return u;
}

// m16n8k8 tf32 HMMA (portable PTX, sm_80+; no arch-specific 'a' features)
__device__ __forceinline__ void mma1688(float c[4], const uint32_t a[4],
                                        uint32_t b0, uint32_t b1) {
    asm volatile(
        "mma.sync.aligned.m16n8k8.row.col.f32.tf32.tf32.f32 "
        "{%0,%1,%2,%3}, {%4,%5,%6,%7}, {%8,%9}, {%0,%1,%2,%3};\n"
        : "+f"(c[0]), "+f"(c[1]), "+f"(c[2]), "+f"(c[3])
        : "r"(a[0]), "r"(a[1]), "r"(a[2]), "r"(a[3]), "r"(b0), "r"(b1));
}

// ============================================================
// Kernel 1: T = features @ W^T  (known-correct R4 version, g_Tt removed)
// ============================================================
__global__ void __launch_bounds__(256) k_transform(const float* __restrict__ feat,
                                                   const float* __restrict__ W) {
    __shared__ float Asm[32][64];
    __shared__ float Bsm[32][64];
    int i0 = blockIdx.x * 64;
    int c0 = blockIdx.y * 64;
    int t = threadIdx.x;
    int tr = t & 15, tc = t >> 4;

    float acc[4][4];
#pragma unroll
    for (int a = 0; a < 4; a++)
#pragma unroll
        for (int b = 0; b < 4; b++) acc[a][b] = 0.f;

    int lrow = t >> 3, lkg = t & 7;
    for (int k0 = 0; k0 < KDIM; k0 += 32) {
        float4 va0 = *(const float4*)&feat[(i0 + lrow) * KDIM + k0 + lkg * 4];
        float4 va1 = *(const float4*)&feat[(i0 + lrow + 32) * KDIM + k0 + lkg * 4];
        float4 vb0 = *(const float4*)&W[(c0 + lrow) * KDIM + k0 + lkg * 4];
        float4 vb1 = *(const float4*)&W[(c0 + lrow + 32) * KDIM + k0 + lkg * 4];
        __syncthreads();
        Asm[lkg * 4 + 0][lrow]      = va0.x; Asm[lkg * 4 + 1][lrow]      = va0.y;
        Asm[lkg * 4 + 2][lrow]      = va0.z; Asm[lkg * 4 + 3][lrow]      = va0.w;
        Asm[lkg * 4 + 0][lrow + 32] = va1.x; Asm[lkg * 4 + 1][lrow + 32] = va1.y;
        Asm[lkg * 4 + 2][lrow + 32] = va1.z; Asm[lkg * 4 + 3][lrow + 32] = va1.w;
        Bsm[lkg * 4 + 0][lrow]      = vb0.x; Bsm[lkg * 4 + 1][lrow]      = vb0.y;
        Bsm[lkg * 4 + 2][lrow]      = vb0.z; Bsm[lkg * 4 + 3][lrow]      = vb0.w;
        Bsm[lkg * 4 + 0][lrow + 32] = vb1.x; Bsm[lkg * 4 + 1][lrow + 32] = vb1.y;
        Bsm[lkg * 4 + 2][lrow + 32] = vb1.z; Bsm[lkg * 4 + 3][lrow + 32] = vb1.w;
        __syncthreads();
#pragma unroll
        for (int kk = 0; kk < 32; kk++) {
            float4 a4 = *(const float4*)&Asm[kk][tr * 4];
            float4 b4 = *(const float4*)&Bsm[kk][tc * 4];
            float aa[4] = {a4.x, a4.y, a4.z, a4.w};
            float bb[4] = {b4.x, b4.y, b4.z, b4.w};
#pragma unroll
            for (int r = 0; r < 4; r++)
#pragma unroll
                for (int c = 0; c < 4; c++)
                    acc[r][c] = fmaf(aa[r], bb[c], acc[r][c]);
        }
    }
#pragma unroll
    for (int r = 0; r < 4; r++) {
        float4 v = make_float4(acc[r][0], acc[r][1], acc[r][2], acc[r][3]);
        *(float4*)&g_T[(i0 + tr * 4 + r) * CDIM + c0 + tc * 4] = v;
    }
}

// ============================================================
// Kernel 2: per-node scores + separable exp factor packs (unchanged)
// ============================================================
__global__ void __launch_bounds__(256) k_scores(const float* __restrict__ attn_src,
                                                const float* __restrict__ attn_dst) {
    __shared__ float as_[CDIM], ad_[CDIM];
    int t = threadIdx.x;
    as_[t] = attn_src[t];
    ad_[t] = attn_dst[t];
    __syncthreads();
    int warp = t >> 5, lane = t & 31;
    int row = blockIdx.x * 8 + warp;

    float s0 = 0.f, s1 = 0.f, d0 = 0.f, d1 = 0.f;
#pragma unroll
    for (int f = lane; f < FDIM; f += 32) {
        float t0 = g_T[row * CDIM + f];
        float t1 = g_T[row * CDIM + FDIM + f];
        s0 = fmaf(t0, as_[f], s0);
        d0 = fmaf(t0, ad_[f], d0);
        s1 = fmaf(t1, as_[FDIM + f], s1);
        d1 = fmaf(t1, ad_[FDIM + f], d1);
    }
#pragma unroll
    for (int o = 16; o > 0; o >>= 1) {
        s0 += __shfl_xor_sync(0xFFFFFFFFu, s0, o);
        s1 += __shfl_xor_sync(0xFFFFFFFFu, s1, o);
        d0 += __shfl_xor_sync(0xFFFFFFFFu, d0, o);
        d1 += __shfl_xor_sync(0xFFFFFFFFu, d1, o);
    }
    if (lane == 0) {
        g_SRCF[row * 2 + 0] = make_float4(s0, expf(s0), expf(0.2f * s0), 0.f);
        g_SRCF[row * 2 + 1] = make_float4(s1, expf(s1), expf(0.2f * s1), 0.f);
        g_DSTF[row * 2 + 0] = make_float4(d0, expf(d0), expf(0.2f * d0), 0.f);
        g_DSTF[row * 2 + 1] = make_float4(d1, expf(d1), expf(0.2f * d1), 0.f);
    }
}

// ============================================================
// Kernel 3: fused aggregation with mma.sync tf32 tensor cores.
// CTA = 64 src rows, 512 threads (16 warps).
// Warp task: rowgroup rg=warp&3 (16 rows), head h=(warp>>2)&1, half hf=warp>>3
//   -> 16x64 output block, acc[8][4] fp32 in registers.
// Per tile: Tsm (tf32, pitch 260) + Psm (tf32, pitch 36) -> 32 HMMAs/warp.
// Smem pitches make all fragment LDS conflict-free ((4k+n) mod 32 distinct).
// ============================================================
#define TS_PITCH 260
#define PS_PITCH 36
#define PS_OFF   (32 * TS_PITCH)            // 8320 u32
#define PS_HEAD  (BM * PS_PITCH)            // 2304 u32
#define SMEM_DYN ((PS_OFF + 2 * PS_HEAD) * 4)   // 51712 B

__global__ void __launch_bounds__(512, 1) k_aggregate(const int* __restrict__ adj,
                                                      float* __restrict__ out) {
    extern __shared__ uint32_t sm[];
    uint32_t* Tsm = sm;               // [32][260] tf32
    uint32_t* Psm = sm + PS_OFF;      // [2][64][36] tf32
    __shared__ float lsm[2][BM];
    __shared__ float4 sDEF[KT][2];

    const int t = threadIdx.x;
    const int i0 = blockIdx.x * BM;
    const int lane = t & 31, warp = t >> 5;

    if (t < 2 * BM) lsm[t >> 6][t & 63] = 0.f;

    // ---- build role: row r (0..63), j-quad jq (0..7) ----
    const int r = t >> 3, jq = t & 7;
    const float4 s0 = g_SRCF[(i0 + r) * 2 + 0];
    const float4 s1 = g_SRCF[(i0 + r) * 2 + 1];
    float lp0 = 0.f, lp1 = 0.f;
    const int* arow = adj + (size_t)(i0 + r) * NN + jq * 4;
    int4 acur = *(const int4*)arow;                 // tile 0 adjacency
    float4 defcur = make_float4(0.f, 0.f, 0.f, 0.f);
    if (t < 2 * KT) defcur = g_DSTF[(t >> 1) * 2 + (t & 1)];

    // ---- mma role ----
    const int rg = warp & 3;            // row group: rows 16rg..16rg+15
    const int h  = (warp >> 2) & 1;     // head
    const int hf = warp >> 3;           // column half (64)
    const int arow0 = 16 * rg + (lane >> 2);
    const int nbase = h * FDIM + hf * 64 + (lane >> 2);
    const uint32_t* Ph = Psm + h * PS_HEAD;

    float acc[8][4];
#pragma unroll
    for (int nb = 0; nb < 8; nb++)
#pragma unroll
        for (int c = 0; c < 4; c++) acc[nb][c] = 0.f;

    for (int tile = 0; tile < NTILE; ++tile) {
        const int j0 = tile * KT;

        // ---- phase A: load T tile (tf32-rounded) + stage dst factors ----
#pragma unroll
        for (int p = 0; p < 4; p++) {
            int idx = t + p * 512;
            int jr = idx >> 6, cg = idx & 63;
            float4 v = *(const float4*)&g_T[(size_t)(j0 + jr) * CDIM + cg * 4];
            uint4 u = make_uint4(f2tf32(v.x), f2tf32(v.y), f2tf32(v.z), f2tf32(v.w));
            *(uint4*)&Tsm[jr * TS_PITCH + cg * 4] = u;
        }
        if (t < 2 * KT) sDEF[t >> 1][t & 1] = defcur;
        // prefetch next tile's adjacency + dst factors
        int4 anext = make_int4(0, 0, 0, 0);
        if (tile + 1 < NTILE) {
            anext = *(const int4*)(arow + j0 + KT);
            if (t < 2 * KT) defcur = g_DSTF[(j0 + KT + (t >> 1)) * 2 + (t & 1)];
        }
        __syncthreads();

        // ---- phase B: build P (separable exp) -> tf32 -> Psm ----
        {
            const int* av = (const int*)&acur;
            uint32_t w0[4], w1[4];
#pragma unroll
            for (int q = 0; q < 4; q++) {
                const int jl = jq * 4 + q;
                const float4 d0 = sDEF[jl][0];
                const float4 d1 = sDEF[jl][1];
                float p0 = 0.f, p1 = 0.f;
                if (av[q] > 0) {
                    p0 = (s0.x + d0.x >= 0.f) ? s0.y * d0.y : s0.z * d0.z;
                    p1 = (s1.x + d1.x >= 0.f) ? s1.y * d1.y : s1.z * d1.z;
                }
                lp0 += p0; lp1 += p1;
                w0[q] = f2tf32(p0);
                w1[q] = f2tf32(p1);
            }
            *(uint4*)&Psm[r * PS_PITCH + jq * 4]           = make_uint4(w0[0], w0[1], w0[2], w0[3]);
            *(uint4*)&Psm[PS_HEAD + r * PS_PITCH + jq * 4] = make_uint4(w1[0], w1[1], w1[2], w1[3]);
        }
        acur = anext;
        __syncthreads();

        // ---- phase C: 32 HMMAs per warp (acc += P_tile @ T_tile) ----
        uint32_t afr[4][4];
#pragma unroll
        for (int kb = 0; kb < 4; kb++) {
            const int c0 = kb * 8 + (lane & 3);
            afr[kb][0] = Ph[arow0 * PS_PITCH + c0];
            afr[kb][1] = Ph[(arow0 + 8) * PS_PITCH + c0];
            afr[kb][2] = Ph[arow0 * PS_PITCH + c0 + 4];
            afr[kb][3] = Ph[(arow0 + 8) * PS_PITCH + c0 + 4];
        }
#pragma unroll
        for (int nb = 0; nb < 8; nb++) {
            const int ncol = nbase + nb * 8;
#pragma unroll
            for (int kb = 0; kb < 4; kb++) {
                const int krow = kb * 8 + (lane & 3);
                uint32_t b0 = Tsm[krow * TS_PITCH + ncol];
                uint32_t b1 = Tsm[(krow + 4) * TS_PITCH + ncol];
                mma1688(acc[nb], afr[kb], b0, b1);
            }
        }
        __syncthreads();   // protect Tsm/Psm before next overwrite
    }

    // ---- row sums ----
    atomicAdd(&lsm[0][r], lp0);
    atomicAdd(&lsm[1][r], lp1);
    __syncthreads();

    // ---- epilogue: normalize, exchange head1 -> head0, write final out ----
    float* ex = (float*)sm;   // reuse smem: [64][128] floats
    const int rowA = 16 * rg + (lane >> 2);
    const int rowB = rowA + 8;
    const float lA = lsm[h][rowA], lB = lsm[h][rowB];
    const float invA = (lA > 0.f) ? 1.f / lA : 0.f;
    const float invB = (lB > 0.f) ? 1.f / lB : 0.f;
    const int colb = hf * 64 + 2 * (lane & 3);

    if (h == 1) {
#pragma unroll
        for (int nb = 0; nb < 8; nb++) {
            const int col = colb + nb * 8;
            *(float2*)&ex[rowA * FDIM + col] = make_float2(acc[nb][0] * invA, acc[nb][1] * invA);
            *(float2*)&ex[rowB * FDIM + col] = make_float2(acc[nb][2] * invB, acc[nb][3] * invB);
        }
    }
    __syncthreads();
    if (h == 0) {
#pragma unroll
        for (int nb = 0; nb < 8; nb++) {
            const int col = colb + nb * 8;
            float2 e0 = *(const float2*)&ex[rowA * FDIM + col];
            float2 e1 = *(const float2*)&ex[rowB * FDIM + col];
            float2 oA = make_float2(0.5f * (acc[nb][0] * invA + e0.x),
                                    0.5f * (acc[nb][1] * invA + e0.y));
            float2 oB = make_float2(0.5f * (acc[nb][2] * invB + e1.x),
                                    0.5f * (acc[nb][3] * invB + e1.y));
            *(float2*)&out[(size_t)(i0 + rowA) * FDIM + col] = oA;
            *(float2*)&out[(size_t)(i0 + rowB) * FDIM + col] = oB;
        }
    }
}

// ============================================================
extern "C" void kernel_launch(void* const* d_in, const int* in_sizes, int n_in,
                              void* d_out, int out_size) {
    const float* feat = (const float*)d_in[0];
    const int*   adj  = (const int*)d_in[1];
    const float* W    = (const float*)d_in[2];
    const float* asrc = (const float*)d_in[3];
    const float* adst = (const float*)d_in[4];
    float* out = (float*)d_out;

    cudaFuncSetAttribute(k_aggregate, cudaFuncAttributeMaxDynamicSharedMemorySize, SMEM_DYN);

    dim3 g1(NN / 64, CDIM / 64);
    k_transform<<<g1, 256>>>(feat, W);
    k_scores<<<NN / 8, 256>>>(asrc, adst);
    k_aggregate<<<NN / BM, 512, SMEM_DYN>>>(adj, out);
}

// round 8
// speedup vs baseline: 2.3685x; 1.4678x over previous
#include <cuda_runtime.h>
#include <cuda_fp16.h>
#include <cstdint>
#include <math.h>

#define NN    8192
#define KDIM  256
#define CDIM  256
#define FDIM  128
#define KT    32          // dst-tile width (k of the P@T GEMM)
#define BM    64          // src rows per CTA
#define NTILE (NN / KT)   // 256
#define PB    40          // smem row pitch in halfs (bank-conflict-free: 20q+c distinct mod 32)

// ---- scratch (device globals) ----
__device__ float  g_T  [NN * CDIM];       // transformed [i][h*128+f] fp32 (for k_scores)
__device__ __half g_Thb[NN * CDIM];       // blocked fp16: [j/32][c(256)][j%32]
__device__ float4 g_SRCF[NN * 2];         // {S, e^S, e^{.2S}, 0} per (node, head)
__device__ float4 g_DSTF[NN * 2];         // {D, e^D, e^{.2D}, 0} per (node, head)

// fp16 m16n8k16 HMMA (portable PTX, sm_80+)
__device__ __forceinline__ void mma16816(float c[4], const uint32_t a[4],
                                         uint32_t b0, uint32_t b1) {
    asm volatile(
        "mma.sync.aligned.m16n8k16.row.col.f32.f16.f16.f32 "
        "{%0,%1,%2,%3}, {%4,%5,%6,%7}, {%8,%9}, {%0,%1,%2,%3};\n"
        : "+f"(c[0]), "+f"(c[1]), "+f"(c[2]), "+f"(c[3])
        : "r"(a[0]), "r"(a[1]), "r"(a[2]), "r"(a[3]), "r"(b0), "r"(b1));
}

// ============================================================
// Kernel 1: T = features @ W^T; writes g_T (fp32) + g_Thb (fp16 blocked)
// ============================================================
__global__ void __launch_bounds__(256) k_transform(const float* __restrict__ feat,
                                                   const float* __restrict__ W) {
    __shared__ float Asm[32][64];
    __shared__ float Bsm[32][64];
    int i0 = blockIdx.x * 64;
    int c0 = blockIdx.y * 64;
    int t = threadIdx.x;
    int tr = t & 15, tc = t >> 4;

    float acc[4][4];
#pragma unroll
    for (int a = 0; a < 4; a++)
#pragma unroll
        for (int b = 0; b < 4; b++) acc[a][b] = 0.f;

    int lrow = t >> 3, lkg = t & 7;
    for (int k0 = 0; k0 < KDIM; k0 += 32) {
        float4 va0 = *(const float4*)&feat[(i0 + lrow) * KDIM + k0 + lkg * 4];
        float4 va1 = *(const float4*)&feat[(i0 + lrow + 32) * KDIM + k0 + lkg * 4];
        float4 vb0 = *(const float4*)&W[(c0 + lrow) * KDIM + k0 + lkg * 4];
        float4 vb1 = *(const float4*)&W[(c0 + lrow + 32) * KDIM + k0 + lkg * 4];
        __syncthreads();
        Asm[lkg * 4 + 0][lrow]      = va0.x; Asm[lkg * 4 + 1][lrow]      = va0.y;
        Asm[lkg * 4 + 2][lrow]      = va0.z; Asm[lkg * 4 + 3][lrow]      = va0.w;
        Asm[lkg * 4 + 0][lrow + 32] = va1.x; Asm[lkg * 4 + 1][lrow + 32] = va1.y;
        Asm[lkg * 4 + 2][lrow + 32] = va1.z; Asm[lkg * 4 + 3][lrow + 32] = va1.w;
        Bsm[lkg * 4 + 0][lrow]      = vb0.x; Bsm[lkg * 4 + 1][lrow]      = vb0.y;
        Bsm[lkg * 4 + 2][lrow]      = vb0.z; Bsm[lkg * 4 + 3][lrow]      = vb0.w;
        Bsm[lkg * 4 + 0][lrow + 32] = vb1.x; Bsm[lkg * 4 + 1][lrow + 32] = vb1.y;
        Bsm[lkg * 4 + 2][lrow + 32] = vb1.z; Bsm[lkg * 4 + 3][lrow + 32] = vb1.w;
        __syncthreads();
#pragma unroll
        for (int kk = 0; kk < 32; kk++) {
            float4 a4 = *(const float4*)&Asm[kk][tr * 4];
            float4 b4 = *(const float4*)&Bsm[kk][tc * 4];
            float aa[4] = {a4.x, a4.y, a4.z, a4.w};
            float bb[4] = {b4.x, b4.y, b4.z, b4.w};
#pragma unroll
            for (int r = 0; r < 4; r++)
#pragma unroll
                for (int c = 0; c < 4; c++)
                    acc[r][c] = fmaf(aa[r], bb[c], acc[r][c]);
        }
    }
#pragma unroll
    for (int r = 0; r < 4; r++) {
        float4 v = make_float4(acc[r][0], acc[r][1], acc[r][2], acc[r][3]);
        *(float4*)&g_T[(size_t)(i0 + tr * 4 + r) * CDIM + c0 + tc * 4] = v;
    }
    // blocked fp16 copy: g_Thb[jt][c][jk], jt = j/32, jk = j%32
    {
        int jt = (i0 >> 5) + (tr >> 3);
        int jk = (tr * 4) & 31;
#pragma unroll
        for (int cc = 0; cc < 4; cc++) {
            int c = c0 + tc * 4 + cc;
            __half2 h01 = __floats2half2_rn(acc[0][cc], acc[1][cc]);
            __half2 h23 = __floats2half2_rn(acc[2][cc], acc[3][cc]);
            uint2 v;
            v.x = *(uint32_t*)&h01;
            v.y = *(uint32_t*)&h23;
            *(uint2*)&g_Thb[(size_t)jt * 8192 + c * 32 + jk] = v;
        }
    }
}

// ============================================================
// Kernel 2: per-node scores + separable exp factor packs
// ============================================================
__global__ void __launch_bounds__(256) k_scores(const float* __restrict__ attn_src,
                                                const float* __restrict__ attn_dst) {
    __shared__ float as_[CDIM], ad_[CDIM];
    int t = threadIdx.x;
    as_[t] = attn_src[t];
    ad_[t] = attn_dst[t];
    __syncthreads();
    int warp = t >> 5, lane = t & 31;
    int row = blockIdx.x * 8 + warp;

    float s0 = 0.f, s1 = 0.f, d0 = 0.f, d1 = 0.f;
#pragma unroll
    for (int f = lane; f < FDIM; f += 32) {
        float t0 = g_T[(size_t)row * CDIM + f];
        float t1 = g_T[(size_t)row * CDIM + FDIM + f];
        s0 = fmaf(t0, as_[f], s0);
        d0 = fmaf(t0, ad_[f], d0);
        s1 = fmaf(t1, as_[FDIM + f], s1);
        d1 = fmaf(t1, ad_[FDIM + f], d1);
    }
#pragma unroll
    for (int o = 16; o > 0; o >>= 1) {
        s0 += __shfl_xor_sync(0xFFFFFFFFu, s0, o);
        s1 += __shfl_xor_sync(0xFFFFFFFFu, s1, o);
        d0 += __shfl_xor_sync(0xFFFFFFFFu, d0, o);
        d1 += __shfl_xor_sync(0xFFFFFFFFu, d1, o);
    }
    if (lane == 0) {
        g_SRCF[row * 2 + 0] = make_float4(s0, expf(s0), expf(0.2f * s0), 0.f);
        g_SRCF[row * 2 + 1] = make_float4(s1, expf(s1), expf(0.2f * s1), 0.f);
        g_DSTF[row * 2 + 0] = make_float4(d0, expf(d0), expf(0.2f * d0), 0.f);
        g_DSTF[row * 2 + 1] = make_float4(d1, expf(d1), expf(0.2f * d1), 0.f);
    }
}

// ============================================================
// Kernel 3: fused aggregation, fp16 m16n8k16, single-barrier pipeline.
// 512 thr = 16 warps: rg=warp&1 (32 rows), h=(warp>>1)&1, cs=warp>>2 (32 cols).
// Double-buffered Tsm (256 x PB halfs) and Psm (2 x 64 x PB halfs).
// ============================================================
#define TS_BUF (256 * PB)              // 10240 halfs
#define PS_BUF (2 * 64 * PB)           // 5120 halfs
#define SMEM_DYN ((2 * TS_BUF + 2 * PS_BUF) * 2)   // 61440 B

__global__ void __launch_bounds__(512, 1) k_aggregate(const int* __restrict__ adj,
                                                      float* __restrict__ out) {
    extern __shared__ __align__(16) __half dyn[];
    __shared__ float4 sDEF[4][KT][2];    // 4-slot ring of dst factors
    __shared__ float  lsm[2][BM];

    const int t = threadIdx.x;
    const int i0 = blockIdx.x * BM;
    const int lane = t & 31, warp = t >> 5;
    const int q = lane >> 2, cl = lane & 3;

    // mma roles
    const int rg = warp & 1;
    const int h  = (warp >> 1) & 1;
    const int cs = warp >> 2;
    const int r0 = 32 * rg + q;

    // builder role
    const int br = t >> 3, bjq = t & 7;

    if (t < 2 * BM) lsm[t >> 6][t & 63] = 0.f;

    const float4 s0 = g_SRCF[(i0 + br) * 2 + 0];
    const float4 s1 = g_SRCF[(i0 + br) * 2 + 1];
    float lp0 = 0.f, lp1 = 0.f;
    const int* arow = adj + (size_t)(i0 + br) * NN + bjq * 4;

    // prologue prefetch: tile-0 adjacency, sDEF slot 0 (tile 0), defcur (tile 1)
    int4 acur = *(const int4*)arow;
    float4 defcur = make_float4(0.f, 0.f, 0.f, 0.f);
    if (t < 2 * KT) {
        sDEF[0][t >> 1][t & 1] = g_DSTF[(t >> 1) * 2 + (t & 1)];
        defcur = g_DSTF[(KT + (t >> 1)) * 2 + (t & 1)];
    }

    float acc[2][4][4];
#pragma unroll
    for (int mf = 0; mf < 2; mf++)
#pragma unroll
        for (int nb = 0; nb < 4; nb++)
#pragma unroll
            for (int c = 0; c < 4; c++) acc[mf][nb][c] = 0.f;

    __syncthreads();

    for (int tile = 0; tile < NTILE; ++tile) {
        const int s = tile & 1;
        __half* Ts = dyn + s * TS_BUF;
        __half* Ps = dyn + 2 * TS_BUF + s * PS_BUF;

        // ================= phase W (writes into buffer s) =================
        // B copy: contiguous 16KB block g_Thb[tile] -> Tsm (pitch PB)
        {
            const __half* src = g_Thb + (size_t)tile * 8192;
#pragma unroll
            for (int p = 0; p < 2; p++) {
                int chunk = t + p * 512;                 // 0..1023
                int c = chunk >> 2, kc = chunk & 3;
                uint4 v = *(const uint4*)(src + chunk * 8);
                *(uint4*)(Ts + c * PB + kc * 8) = v;
            }
        }
        // stage sDEF for tile+1
        if (t < 2 * KT && tile + 1 < NTILE)
            sDEF[(tile + 1) & 3][t >> 1][t & 1] = defcur;

        // build P (separable exp) -> fp16 -> Psm
        {
            const float4* dslot0 = &sDEF[tile & 3][bjq * 4][0];
            const int* av = (const int*)&acur;
            float p0[4], p1[4];
#pragma unroll
            for (int qq = 0; qq < 4; qq++) {
                const float4 d0 = dslot0[qq * 2 + 0];
                const float4 d1 = dslot0[qq * 2 + 1];
                float v0 = 0.f, v1 = 0.f;
                if (av[qq] > 0) {
                    v0 = (s0.x + d0.x >= 0.f) ? s0.y * d0.y : s0.z * d0.z;
                    v1 = (s1.x + d1.x >= 0.f) ? s1.y * d1.y : s1.z * d1.z;
                }
                lp0 += v0; lp1 += v1;
                p0[qq] = v0; p1[qq] = v1;
            }
            __half2 a01 = __floats2half2_rn(p0[0], p0[1]);
            __half2 a23 = __floats2half2_rn(p0[2], p0[3]);
            __half2 b01 = __floats2half2_rn(p1[0], p1[1]);
            __half2 b23 = __floats2half2_rn(p1[2], p1[3]);
            uint2 u0, u1;
            u0.x = *(uint32_t*)&a01; u0.y = *(uint32_t*)&a23;
            u1.x = *(uint32_t*)&b01; u1.y = *(uint32_t*)&b23;
            *(uint2*)(Ps + br * PB + bjq * 4)            = u0;   // head 0
            *(uint2*)(Ps + 64 * PB + br * PB + bjq * 4)  = u1;   // head 1
        }
        // prefetch next adjacency + dst factors (latency spans the barrier)
        int4 anext = make_int4(0, 0, 0, 0);
        if (tile + 1 < NTILE) anext = *(const int4*)(arow + (tile + 1) * KT);
        if (t < 2 * KT && tile + 2 < NTILE)
            defcur = g_DSTF[((tile + 2) * KT + (t >> 1)) * 2 + (t & 1)];

        __syncthreads();

        // ================= phase R (reads buffer s, HMMA) =================
        {
            const __half* Ph = Ps + h * (64 * PB);
            uint32_t afr[2][2][4];
#pragma unroll
            for (int mf = 0; mf < 2; mf++) {
                const int ra = r0 + 16 * mf;
#pragma unroll
                for (int kb = 0; kb < 2; kb++) {
                    const __half* pa = Ph + kb * 16 + 2 * cl;
                    afr[mf][kb][0] = *(const uint32_t*)(pa + ra * PB);
                    afr[mf][kb][1] = *(const uint32_t*)(pa + (ra + 8) * PB);
                    afr[mf][kb][2] = *(const uint32_t*)(pa + ra * PB + 8);
                    afr[mf][kb][3] = *(const uint32_t*)(pa + (ra + 8) * PB + 8);
                }
            }
#pragma unroll
            for (int nb = 0; nb < 4; nb++) {
                const int ncol = h * FDIM + cs * 32 + nb * 8 + q;
                const __half* pb = Ts + ncol * PB + 2 * cl;
#pragma unroll
                for (int kb = 0; kb < 2; kb++) {
                    uint32_t b0 = *(const uint32_t*)(pb + kb * 16);
                    uint32_t b1 = *(const uint32_t*)(pb + kb * 16 + 8);
                    mma16816(acc[0][nb], afr[0][kb], b0, b1);
                    mma16816(acc[1][nb], afr[1][kb], b0, b1);
                }
            }
        }
        acur = anext;
    }

    // ---- row sums ----
    atomicAdd(&lsm[0][br], lp0);
    atomicAdd(&lsm[1][br], lp1);
    __syncthreads();

    // ---- epilogue: normalize, head exchange via smem, head-mean, store ----
    float* ex = (float*)dyn;    // 64 x 128 fp32 = 32KB (buffers no longer needed)
    if (h == 1) {
#pragma unroll
        for (int mf = 0; mf < 2; mf++) {
            const int rowA = 32 * rg + 16 * mf + q;
            const int rowB = rowA + 8;
            const float lA = lsm[1][rowA], lB = lsm[1][rowB];
            const float iA = (lA > 0.f) ? 1.f / lA : 0.f;
            const float iB = (lB > 0.f) ? 1.f / lB : 0.f;
#pragma unroll
            for (int nb = 0; nb < 4; nb++) {
                const int colf = cs * 32 + nb * 8 + 2 * cl;
                *(float2*)&ex[rowA * FDIM + colf] =
                    make_float2(acc[mf][nb][0] * iA, acc[mf][nb][1] * iA);
                *(float2*)&ex[rowB * FDIM + colf] =
                    make_float2(acc[mf][nb][2] * iB, acc[mf][nb][3] * iB);
            }
        }
    }
    __syncthreads();
    if (h == 0) {
#pragma unroll
        for (int mf = 0; mf < 2; mf++) {
            const int rowA = 32 * rg + 16 * mf + q;
            const int rowB = rowA + 8;
            const float lA = lsm[0][rowA], lB = lsm[0][rowB];
            const float iA = (lA > 0.f) ? 1.f / lA : 0.f;
            const float iB = (lB > 0.f) ? 1.f / lB : 0.f;
#pragma unroll
            for (int nb = 0; nb < 4; nb++) {
                const int colf = cs * 32 + nb * 8 + 2 * cl;
                float2 e0 = *(const float2*)&ex[rowA * FDIM + colf];
                float2 e1 = *(const float2*)&ex[rowB * FDIM + colf];
                float2 oA = make_float2(0.5f * (acc[mf][nb][0] * iA + e0.x),
                                        0.5f * (acc[mf][nb][1] * iA + e0.y));
                float2 oB = make_float2(0.5f * (acc[mf][nb][2] * iB + e1.x),
                                        0.5f * (acc[mf][nb][3] * iB + e1.y));
                *(float2*)&out[(size_t)(i0 + rowA) * FDIM + colf] = oA;
                *(float2*)&out[(size_t)(i0 + rowB) * FDIM + colf] = oB;
            }
        }
    }
}

// ============================================================
extern "C" void kernel_launch(void* const* d_in, const int* in_sizes, int n_in,
                              void* d_out, int out_size) {
    const float* feat = (const float*)d_in[0];
    const int*   adj  = (const int*)d_in[1];
    const float* W    = (const float*)d_in[2];
    const float* asrc = (const float*)d_in[3];
    const float* adst = (const float*)d_in[4];
    float* out = (float*)d_out;

    cudaFuncSetAttribute(k_aggregate, cudaFuncAttributeMaxDynamicSharedMemorySize, SMEM_DYN);

    dim3 g1(NN / 64, CDIM / 64);
    k_transform<<<g1, 256>>>(feat, W);
    k_scores<<<NN / 8, 256>>>(asrc, adst);
    k_aggregate<<<NN / BM, 512, SMEM_DYN>>>(adj, out);
}

// round 9
// speedup vs baseline: 4.6167x; 1.9492x over previous
#include <cuda_runtime.h>
#include <cuda_fp16.h>
#include <cstdint>
#include <math.h>

#define NN    8192
#define KDIM  256
#define CDIM  256
#define FDIM  128
#define KT2   64          // dst-tile width
#define BM    64          // src rows per CTA
#define NT2   (NN / KT2)  // 128 tiles
#define PB2   72          // smem pitch in halfs (36 words == 4 mod 32 -> conflict-free frags)

// ---- scratch (device globals) ----
__device__ float  g_T  [NN * CDIM];       // transformed [i][h*128+f] fp32 (for k_scores)
__device__ __half g_Thb[NN * CDIM];       // blocked fp16: [j/64][c(256)][j%64]
__device__ float4 g_SRCF[NN * 2];         // {S, e^S, e^{.2S}, 0} per (node, head)
__device__ float4 g_DSTF[NN * 2];         // {D, e^D, e^{.2D}, 0} per (node, head)

// fp16 m16n8k16 HMMA (portable PTX, sm_80+)
__device__ __forceinline__ void mma16816(float c[4], const uint32_t a[4],
                                         uint32_t b0, uint32_t b1) {
    asm volatile(
        "mma.sync.aligned.m16n8k16.row.col.f32.f16.f16.f32 "
        "{%0,%1,%2,%3}, {%4,%5,%6,%7}, {%8,%9}, {%0,%1,%2,%3};\n"
        : "+f"(c[0]), "+f"(c[1]), "+f"(c[2]), "+f"(c[3])
        : "r"(a[0]), "r"(a[1]), "r"(a[2]), "r"(a[3]), "r"(b0), "r"(b1));
}

// ============================================================
// Kernel 1: T = features @ W^T; writes g_T (fp32) + g_Thb (fp16, 64-blocked)
// ============================================================
__global__ void __launch_bounds__(256) k_transform(const float* __restrict__ feat,
                                                   const float* __restrict__ W) {
    __shared__ float Asm[32][64];
    __shared__ float Bsm[32][64];
    int i0 = blockIdx.x * 64;
    int c0 = blockIdx.y * 64;
    int t = threadIdx.x;
    int tr = t & 15, tc = t >> 4;

    float acc[4][4];
#pragma unroll
    for (int a = 0; a < 4; a++)
#pragma unroll
        for (int b = 0; b < 4; b++) acc[a][b] = 0.f;

    int lrow = t >> 3, lkg = t & 7;
    for (int k0 = 0; k0 < KDIM; k0 += 32) {
        float4 va0 = *(const float4*)&feat[(i0 + lrow) * KDIM + k0 + lkg * 4];
        float4 va1 = *(const float4*)&feat[(i0 + lrow + 32) * KDIM + k0 + lkg * 4];
        float4 vb0 = *(const float4*)&W[(c0 + lrow) * KDIM + k0 + lkg * 4];
        float4 vb1 = *(const float4*)&W[(c0 + lrow + 32) * KDIM + k0 + lkg * 4];
        __syncthreads();
        Asm[lkg * 4 + 0][lrow]      = va0.x; Asm[lkg * 4 + 1][lrow]      = va0.y;
        Asm[lkg * 4 + 2][lrow]      = va0.z; Asm[lkg * 4 + 3][lrow]      = va0.w;
        Asm[lkg * 4 + 0][lrow + 32] = va1.x; Asm[lkg * 4 + 1][lrow + 32] = va1.y;
        Asm[lkg * 4 + 2][lrow + 32] = va1.z; Asm[lkg * 4 + 3][lrow + 32] = va1.w;
        Bsm[lkg * 4 + 0][lrow]      = vb0.x; Bsm[lkg * 4 + 1][lrow]      = vb0.y;
        Bsm[lkg * 4 + 2][lrow]      = vb0.z; Bsm[lkg * 4 + 3][lrow]      = vb0.w;
        Bsm[lkg * 4 + 0][lrow + 32] = vb1.x; Bsm[lkg * 4 + 1][lrow + 32] = vb1.y;
        Bsm[lkg * 4 + 2][lrow + 32] = vb1.z; Bsm[lkg * 4 + 3][lrow + 32] = vb1.w;
        __syncthreads();
#pragma unroll
        for (int kk = 0; kk < 32; kk++) {
            float4 a4 = *(const float4*)&Asm[kk][tr * 4];
            float4 b4 = *(const float4*)&Bsm[kk][tc * 4];
            float aa[4] = {a4.x, a4.y, a4.z, a4.w};
            float bb[4] = {b4.x, b4.y, b4.z, b4.w};
#pragma unroll
            for (int r = 0; r < 4; r++)
#pragma unroll
                for (int c = 0; c < 4; c++)
                    acc[r][c] = fmaf(aa[r], bb[c], acc[r][c]);
        }
    }
#pragma unroll
    for (int r = 0; r < 4; r++) {
        float4 v = make_float4(acc[r][0], acc[r][1], acc[r][2], acc[r][3]);
        *(float4*)&g_T[(size_t)(i0 + tr * 4 + r) * CDIM + c0 + tc * 4] = v;
    }
    // blocked fp16 copy: g_Thb[j/64][c][j%64]; this CTA covers exactly one 64-block
    {
        const size_t blk = (size_t)(i0 >> 6) * 16384;
#pragma unroll
        for (int cc = 0; cc < 4; cc++) {
            int c = c0 + tc * 4 + cc;
            __half2 h01 = __floats2half2_rn(acc[0][cc], acc[1][cc]);
            __half2 h23 = __floats2half2_rn(acc[2][cc], acc[3][cc]);
            uint2 v;
            v.x = *(uint32_t*)&h01;
            v.y = *(uint32_t*)&h23;
            *(uint2*)&g_Thb[blk + c * 64 + tr * 4] = v;
        }
    }
}

// ============================================================
// Kernel 2: per-node scores + separable exp factor packs
// ============================================================
__global__ void __launch_bounds__(256) k_scores(const float* __restrict__ attn_src,
                                                const float* __restrict__ attn_dst) {
    __shared__ float as_[CDIM], ad_[CDIM];
    int t = threadIdx.x;
    as_[t] = attn_src[t];
    ad_[t] = attn_dst[t];
    __syncthreads();
    int warp = t >> 5, lane = t & 31;
    int row = blockIdx.x * 8 + warp;

    float s0 = 0.f, s1 = 0.f, d0 = 0.f, d1 = 0.f;
#pragma unroll
    for (int f = lane; f < FDIM; f += 32) {
        float t0 = g_T[(size_t)row * CDIM + f];
        float t1 = g_T[(size_t)row * CDIM + FDIM + f];
        s0 = fmaf(t0, as_[f], s0);
        d0 = fmaf(t0, ad_[f], d0);
        s1 = fmaf(t1, as_[FDIM + f], s1);
        d1 = fmaf(t1, ad_[FDIM + f], d1);
    }
#pragma unroll
    for (int o = 16; o > 0; o >>= 1) {
        s0 += __shfl_xor_sync(0xFFFFFFFFu, s0, o);
        s1 += __shfl_xor_sync(0xFFFFFFFFu, s1, o);
        d0 += __shfl_xor_sync(0xFFFFFFFFu, d0, o);
        d1 += __shfl_xor_sync(0xFFFFFFFFu, d1, o);
    }
    if (lane == 0) {
        g_SRCF[row * 2 + 0] = make_float4(s0, expf(s0), expf(0.2f * s0), 0.f);
        g_SRCF[row * 2 + 1] = make_float4(s1, expf(s1), expf(0.2f * s1), 0.f);
        g_DSTF[row * 2 + 0] = make_float4(d0, expf(d0), expf(0.2f * d0), 0.f);
        g_DSTF[row * 2 + 1] = make_float4(d1, expf(d1), expf(0.2f * d1), 0.f);
    }
}

// ============================================================
// Kernel 3: fp16 m16n8k16 aggregation, KT=64, one barrier per tile.
// Dynamic smem (halfs): Ts[2][256*72], Ps[2][2*64*72], then dSoA floats.
// ============================================================
#define TS_SZ  (256 * PB2)                  // 18432 halfs per buffer
#define PS_SZ  (2 * 64 * PB2)               // 9216 halfs per buffer
#define DSOA_OFF (2 * TS_SZ + 2 * PS_SZ)    // 55296 halfs (byte 110592; word%32==0)
#define SMEM_DYN (DSOA_OFF * 2 + 2 * 2 * 3 * 64 * 4)   // 113664 B

__global__ void __launch_bounds__(512, 1) k_aggregate(const int* __restrict__ adj,
                                                      float* __restrict__ out) {
    extern __shared__ __align__(16) __half dyn[];
    float* dS = (float*)(dyn + DSOA_OFF);           // [slot][head][arr][64]
    __shared__ float lsm[2][BM];

    const int t = threadIdx.x;
    const int i0 = blockIdx.x * BM;
    const int lane = t & 31, warp = t >> 5;
    const int q = lane >> 2, cl = lane & 3;

    // mma roles: rows 32*rg.., head h, cols 32*cs..
    const int rg = warp & 1;
    const int h  = (warp >> 1) & 1;
    const int cs = warp >> 2;

    // builder role: row br, j-quads bjq and bjq+8
    const int br = t >> 3, bjq = t & 7;

    if (t < 2 * BM) lsm[t >> 6][t & 63] = 0.f;

    const float4 s0 = g_SRCF[(i0 + br) * 2 + 0];
    const float4 s1 = g_SRCF[(i0 + br) * 2 + 1];
    float lp0 = 0.f, lp1 = 0.f;
    const int* arow = adj + (size_t)(i0 + br) * NN;

    // ---- prologue prefetch ----
    uint4 Tpre[4];
#pragma unroll
    for (int p = 0; p < 4; p++)
        Tpre[p] = *(const uint4*)(g_Thb + (size_t)(t + p * 512) * 8);
    int4 acur[2];
    acur[0] = *(const int4*)(arow + 4 * bjq);
    acur[1] = *(const int4*)(arow + 4 * (bjq + 8));
    float4 dpre = make_float4(0.f, 0.f, 0.f, 0.f);
    if (t < 128) {
        const int j = t & 63, h2 = t >> 6;
        float4 v0 = g_DSTF[j * 2 + h2];              // tile 0 -> slot 0
        float* a0 = dS + (0 * 2 + h2) * 3 * 64;
        a0[0 * 64 + j] = v0.x;
        a0[1 * 64 + j] = v0.y;
        a0[2 * 64 + j] = v0.z;
        dpre = g_DSTF[(64 + j) * 2 + h2];            // tile 1
    }

    float acc[2][4][4];
#pragma unroll
    for (int mf = 0; mf < 2; mf++)
#pragma unroll
        for (int nb = 0; nb < 4; nb++)
#pragma unroll
            for (int c = 0; c < 4; c++) acc[mf][nb][c] = 0.f;

    __syncthreads();

    for (int tile = 0; tile < NT2; ++tile) {
        const int s = tile & 1;
        __half* Ts = dyn + s * TS_SZ;
        __half* Ps = dyn + 2 * TS_SZ + s * PS_SZ;

        // ---- publish T tile from prefetch regs ----
#pragma unroll
        for (int p = 0; p < 4; p++) {
            int chunk = t + p * 512;
            int c = chunk >> 3, kc = chunk & 7;
            *(uint4*)(Ts + c * PB2 + kc * 8) = Tpre[p];
        }
        // prefetch next T tile
        if (tile + 1 < NT2) {
            const __half* src = g_Thb + (size_t)(tile + 1) * 16384;
#pragma unroll
            for (int p = 0; p < 4; p++)
                Tpre[p] = *(const uint4*)(src + (size_t)(t + p * 512) * 8);
        }
        // stage dst-factor SoA for tile+1, prefetch tile+2
        if (t < 128 && tile + 1 < NT2) {
            const int j = t & 63, h2 = t >> 6;
            float* a0 = dS + (((tile + 1) & 1) * 2 + h2) * 3 * 64;
            a0[0 * 64 + j] = dpre.x;
            a0[1 * 64 + j] = dpre.y;
            a0[2 * 64 + j] = dpre.z;
            if (tile + 2 < NT2) dpre = g_DSTF[((tile + 2) * 64 + j) * 2 + h2];
        }

        // ---- build P (separable exp) -> fp16 -> Ps ----
#pragma unroll
        for (int g = 0; g < 2; g++) {
            const int j4 = bjq + 8 * g;
            const int* av = (const int*)&acur[g];
            const float* b0p = dS + (s * 2 + 0) * 3 * 64;
            const float* b1p = dS + (s * 2 + 1) * 3 * 64;
            float4 D0 = *(const float4*)(b0p + 0 * 64 + 4 * j4);
            float4 E0 = *(const float4*)(b0p + 1 * 64 + 4 * j4);
            float4 F0 = *(const float4*)(b0p + 2 * 64 + 4 * j4);
            float4 D1 = *(const float4*)(b1p + 0 * 64 + 4 * j4);
            float4 E1 = *(const float4*)(b1p + 1 * 64 + 4 * j4);
            float4 F1 = *(const float4*)(b1p + 2 * 64 + 4 * j4);
            float Da0[4] = {D0.x, D0.y, D0.z, D0.w};
            float Ea0[4] = {E0.x, E0.y, E0.z, E0.w};
            float Fa0[4] = {F0.x, F0.y, F0.z, F0.w};
            float Da1[4] = {D1.x, D1.y, D1.z, D1.w};
            float Ea1[4] = {E1.x, E1.y, E1.z, E1.w};
            float Fa1[4] = {F1.x, F1.y, F1.z, F1.w};
            float p0[4], p1[4];
#pragma unroll
            for (int qq = 0; qq < 4; qq++) {
                float v0 = 0.f, v1 = 0.f;
                if (av[qq] > 0) {
                    v0 = (s0.x + Da0[qq] >= 0.f) ? s0.y * Ea0[qq] : s0.z * Fa0[qq];
                    v1 = (s1.x + Da1[qq] >= 0.f) ? s1.y * Ea1[qq] : s1.z * Fa1[qq];
                }
                lp0 += v0; lp1 += v1;
                p0[qq] = v0; p1[qq] = v1;
            }
            __half2 a01 = __floats2half2_rn(p0[0], p0[1]);
            __half2 a23 = __floats2half2_rn(p0[2], p0[3]);
            __half2 c01 = __floats2half2_rn(p1[0], p1[1]);
            __half2 c23 = __floats2half2_rn(p1[2], p1[3]);
            uint2 u0, u1;
            u0.x = *(uint32_t*)&a01; u0.y = *(uint32_t*)&a23;
            u1.x = *(uint32_t*)&c01; u1.y = *(uint32_t*)&c23;
            *(uint2*)(Ps + br * PB2 + 4 * j4)              = u0;   // head 0
            *(uint2*)(Ps + (64 + br) * PB2 + 4 * j4)       = u1;   // head 1
        }
        // prefetch next adjacency
        if (tile + 1 < NT2) {
            const int jb = (tile + 1) * KT2;
            acur[0] = *(const int4*)(arow + jb + 4 * bjq);
            acur[1] = *(const int4*)(arow + jb + 4 * (bjq + 8));
        }

        __syncthreads();

        // ---- HMMA phase ----
        {
            const __half* Ph = Ps + h * (64 * PB2);
#pragma unroll
            for (int kb = 0; kb < 4; kb++) {
                uint32_t afr[2][4];
#pragma unroll
                for (int mf = 0; mf < 2; mf++) {
                    const int ra = 32 * rg + 16 * mf + q;
                    const __half* pa = Ph + ra * PB2 + kb * 16 + 2 * cl;
                    afr[mf][0] = *(const uint32_t*)pa;
                    afr[mf][1] = *(const uint32_t*)(pa + 8 * PB2);
                    afr[mf][2] = *(const uint32_t*)(pa + 8);
                    afr[mf][3] = *(const uint32_t*)(pa + 8 * PB2 + 8);
                }
#pragma unroll
                for (int nb = 0; nb < 4; nb++) {
                    const int ncol = h * FDIM + cs * 32 + nb * 8 + q;
                    const __half* pb = Ts + ncol * PB2 + kb * 16 + 2 * cl;
                    uint32_t b0 = *(const uint32_t*)pb;
                    uint32_t b1 = *(const uint32_t*)(pb + 8);
                    mma16816(acc[0][nb], afr[0], b0, b1);
                    mma16816(acc[1][nb], afr[1], b0, b1);
                }
            }
        }
    }

    // ---- row sums ----
    atomicAdd(&lsm[0][br], lp0);
    atomicAdd(&lsm[1][br], lp1);
    __syncthreads();

    // ---- epilogue: normalize, head exchange via smem, head-mean, store ----
    float* ex = (float*)dyn;    // 64 x 128 fp32 (buffers dead now)
    if (h == 1) {
#pragma unroll
        for (int mf = 0; mf < 2; mf++) {
            const int rowA = 32 * rg + 16 * mf + q;
            const int rowB = rowA + 8;
            const float lA = lsm[1][rowA], lB = lsm[1][rowB];
            const float iA = (lA > 0.f) ? 1.f / lA : 0.f;
            const float iB = (lB > 0.f) ? 1.f / lB : 0.f;
#pragma unroll
            for (int nb = 0; nb < 4; nb++) {
                const int colf = cs * 32 + nb * 8 + 2 * cl;
                *(float2*)&ex[rowA * FDIM + colf] =
                    make_float2(acc[mf][nb][0] * iA, acc[mf][nb][1] * iA);
                *(float2*)&ex[rowB * FDIM + colf] =
                    make_float2(acc[mf][nb][2] * iB, acc[mf][nb][3] * iB);
            }
        }
    }
    __syncthreads();
    if (h == 0) {
#pragma unroll
        for (int mf = 0; mf < 2; mf++) {
            const int rowA = 32 * rg + 16 * mf + q;
            const int rowB = rowA + 8;
            const float lA = lsm[0][rowA], lB = lsm[0][rowB];
            const float iA = (lA > 0.f) ? 1.f / lA : 0.f;
            const float iB = (lB > 0.f) ? 1.f / lB : 0.f;
#pragma unroll
            for (int nb = 0; nb < 4; nb++) {
                const int colf = cs * 32 + nb * 8 + 2 * cl;
                float2 e0 = *(const float2*)&ex[rowA * FDIM + colf];
                float2 e1 = *(const float2*)&ex[rowB * FDIM + colf];
                float2 oA = make_float2(0.5f * (acc[mf][nb][0] * iA + e0.x),
                                        0.5f * (acc[mf][nb][1] * iA + e0.y));
                float2 oB = make_float2(0.5f * (acc[mf][nb][2] * iB + e1.x),
                                        0.5f * (acc[mf][nb][3] * iB + e1.y));
                *(float2*)&out[(size_t)(i0 + rowA) * FDIM + colf] = oA;
                *(float2*)&out[(size_t)(i0 + rowB) * FDIM + colf] = oB;
            }
        }
    }
}

// ============================================================
extern "C" void kernel_launch(void* const* d_in, const int* in_sizes, int n_in,
                              void* d_out, int out_size) {
    const float* feat = (const float*)d_in[0];
    const int*   adj  = (const int*)d_in[1];
    const float* W    = (const float*)d_in[2];
    const float* asrc = (const float*)d_in[3];
    const float* adst = (const float*)d_in[4];
    float* out = (float*)d_out;

    cudaFuncSetAttribute(k_aggregate, cudaFuncAttributeMaxDynamicSharedMemorySize, SMEM_DYN);

    dim3 g1(NN / 64, CDIM / 64);
    k_transform<<<g1, 256>>>(feat, W);
    k_scores<<<NN / 8, 256>>>(asrc, adst);
    k_aggregate<<<NN / BM, 512, SMEM_DYN>>>(adj, out);
}

// round 11
// speedup vs baseline: 5.4874x; 1.1886x over previous
#include <cuda_runtime.h>
#include <cuda_fp16.h>
#include <cstdint>
#include <math.h>

#define NN    8192
#define KDIM  256
#define CDIM  256
#define FDIM  128
#define KT2   64          // dst-tile width
#define BM    64          // src rows per CTA
#define NT2   (NN / KT2)  // 128 tiles
#define PB2   72          // smem pitch in halfs (36 words == 4 mod 32 -> conflict-free)

// ---- scratch (device globals) ----
__device__ float    g_T  [NN * CDIM];     // transformed [i][h*128+f] fp32 (for k_scores)
__device__ __half   g_Thb[NN * CDIM];     // blocked fp16: [j/64][c(256)][j%64]
__device__ uint4    g_hSRC4[NN * 2];      // per (node,head): {S2, (Es-Fs)2, Fs2, 0} half2 packs
__device__ uint32_t g_hD[2 * 3 * (NN / 2)]; // dst halves [head][arr:D,EmF,F][NN] as u32 pairs

__device__ __forceinline__ __half2 u2h(uint32_t u) { return *(__half2*)&u; }

// fp16 m16n8k16 HMMA (portable PTX, sm_80+)
__device__ __forceinline__ void mma16816(float c[4], const uint32_t a[4],
                                         uint32_t b0, uint32_t b1) {
    asm volatile(
        "mma.sync.aligned.m16n8k16.row.col.f32.f16.f16.f32 "
        "{%0,%1,%2,%3}, {%4,%5,%6,%7}, {%8,%9}, {%0,%1,%2,%3};\n"
        : "+f"(c[0]), "+f"(c[1]), "+f"(c[2]), "+f"(c[3])
        : "r"(a[0]), "r"(a[1]), "r"(a[2]), "r"(a[3]), "r"(b0), "r"(b1));
}
// ldmatrix x4 (portable, sm_75+)
__device__ __forceinline__ void ldsm4(uint32_t r[4], uint32_t addr) {
    asm volatile("ldmatrix.sync.aligned.m8n8.x4.shared.b16 {%0,%1,%2,%3}, [%4];"
                 : "=r"(r[0]), "=r"(r[1]), "=r"(r[2]), "=r"(r[3]) : "r"(addr));
}
__device__ __forceinline__ uint32_t smem_u32p(const void* p) {
    return (uint32_t)__cvta_generic_to_shared(p);
}

// ============================================================
// Kernel 1: T = features @ W^T; writes g_T (fp32) + g_Thb (fp16, 64-blocked)
// ============================================================
__global__ void __launch_bounds__(256) k_transform(const float* __restrict__ feat,
                                                   const float* __restrict__ W) {
    __shared__ float Asm[32][64];
    __shared__ float Bsm[32][64];
    int i0 = blockIdx.x * 64;
    int c0 = blockIdx.y * 64;
    int t = threadIdx.x;
    int tr = t & 15, tc = t >> 4;

    float acc[4][4];
#pragma unroll
    for (int a = 0; a < 4; a++)
#pragma unroll
        for (int b = 0; b < 4; b++) acc[a][b] = 0.f;

    int lrow = t >> 3, lkg = t & 7;
    for (int k0 = 0; k0 < KDIM; k0 += 32) {
        float4 va0 = *(const float4*)&feat[(i0 + lrow) * KDIM + k0 + lkg * 4];
        float4 va1 = *(const float4*)&feat[(i0 + lrow + 32) * KDIM + k0 + lkg * 4];
        float4 vb0 = *(const float4*)&W[(c0 + lrow) * KDIM + k0 + lkg * 4];
        float4 vb1 = *(const float4*)&W[(c0 + lrow + 32) * KDIM + k0 + lkg * 4];
        __syncthreads();
        Asm[lkg * 4 + 0][lrow]      = va0.x; Asm[lkg * 4 + 1][lrow]      = va0.y;
        Asm[lkg * 4 + 2][lrow]      = va0.z; Asm[lkg * 4 + 3][lrow]      = va0.w;
        Asm[lkg * 4 + 0][lrow + 32] = va1.x; Asm[lkg * 4 + 1][lrow + 32] = va1.y;
        Asm[lkg * 4 + 2][lrow + 32] = va1.z; Asm[lkg * 4 + 3][lrow + 32] = va1.w;
        Bsm[lkg * 4 + 0][lrow]      = vb0.x; Bsm[lkg * 4 + 1][lrow]      = vb0.y;
        Bsm[lkg * 4 + 2][lrow]      = vb0.z; Bsm[lkg * 4 + 3][lrow]      = vb0.w;
        Bsm[lkg * 4 + 0][lrow + 32] = vb1.x; Bsm[lkg * 4 + 1][lrow + 32] = vb1.y;
        Bsm[lkg * 4 + 2][lrow + 32] = vb1.z; Bsm[lkg * 4 + 3][lrow + 32] = vb1.w;
        __syncthreads();
#pragma unroll
        for (int kk = 0; kk < 32; kk++) {
            float4 a4 = *(const float4*)&Asm[kk][tr * 4];
            float4 b4 = *(const float4*)&Bsm[kk][tc * 4];
            float aa[4] = {a4.x, a4.y, a4.z, a4.w};
            float bb[4] = {b4.x, b4.y, b4.z, b4.w};
#pragma unroll
            for (int r = 0; r < 4; r++)
#pragma unroll
                for (int c = 0; c < 4; c++)
                    acc[r][c] = fmaf(aa[r], bb[c], acc[r][c]);
        }
    }
#pragma unroll
    for (int r = 0; r < 4; r++) {
        float4 v = make_float4(acc[r][0], acc[r][1], acc[r][2], acc[r][3]);
        *(float4*)&g_T[(size_t)(i0 + tr * 4 + r) * CDIM + c0 + tc * 4] = v;
    }
    {
        const size_t blk = (size_t)(i0 >> 6) * 16384;
#pragma unroll
        for (int cc = 0; cc < 4; cc++) {
            int c = c0 + tc * 4 + cc;
            __half2 h01 = __floats2half2_rn(acc[0][cc], acc[1][cc]);
            __half2 h23 = __floats2half2_rn(acc[2][cc], acc[3][cc]);
            uint2 v;
            v.x = *(uint32_t*)&h01;
            v.y = *(uint32_t*)&h23;
            *(uint2*)&g_Thb[blk + c * 64 + tr * 4] = v;
        }
    }
}

// ============================================================
// Kernel 2: scores + packed half2 separable-exp factors
// ============================================================
__global__ void __launch_bounds__(256) k_scores(const float* __restrict__ attn_src,
                                                const float* __restrict__ attn_dst) {
    __shared__ float as_[CDIM], ad_[CDIM];
    int t = threadIdx.x;
    as_[t] = attn_src[t];
    ad_[t] = attn_dst[t];
    __syncthreads();
    int warp = t >> 5, lane = t & 31;
    int row = blockIdx.x * 8 + warp;

    float s0 = 0.f, s1 = 0.f, d0 = 0.f, d1 = 0.f;
#pragma unroll
    for (int f = lane; f < FDIM; f += 32) {
        float t0 = g_T[(size_t)row * CDIM + f];
        float t1 = g_T[(size_t)row * CDIM + FDIM + f];
        s0 = fmaf(t0, as_[f], s0);
        d0 = fmaf(t0, ad_[f], d0);
        s1 = fmaf(t1, as_[FDIM + f], s1);
        d1 = fmaf(t1, ad_[FDIM + f], d1);
    }
#pragma unroll
    for (int o = 16; o > 0; o >>= 1) {
        s0 += __shfl_xor_sync(0xFFFFFFFFu, s0, o);
        s1 += __shfl_xor_sync(0xFFFFFFFFu, s1, o);
        d0 += __shfl_xor_sync(0xFFFFFFFFu, d0, o);
        d1 += __shfl_xor_sync(0xFFFFFFFFu, d1, o);
    }
    if (lane == 0) {
        float Ss[2] = {s0, s1}, Dd[2] = {d0, d1};
        __half* hb = (__half*)g_hD;
#pragma unroll
        for (int h = 0; h < 2; h++) {
            float S = Ss[h], D = Dd[h];
            float Es = expf(S), Fs = expf(0.2f * S);
            float Ed = expf(D), Fd = expf(0.2f * D);
            __half2 a = __floats2half2_rn(S, S);
            __half2 b = __floats2half2_rn(Es - Fs, Es - Fs);
            __half2 c = __floats2half2_rn(Fs, Fs);
            uint4 u;
            u.x = *(uint32_t*)&a; u.y = *(uint32_t*)&b; u.z = *(uint32_t*)&c; u.w = 0;
            g_hSRC4[row * 2 + h] = u;
            hb[(h * 3 + 0) * NN + row] = __float2half_rn(D);
            hb[(h * 3 + 1) * NN + row] = __float2half_rn(Ed - Fd);
            hb[(h * 3 + 2) * NN + row] = __float2half_rn(Fd);
        }
    }
}

// ============================================================
// Kernel 3: fp16 m16n8k16 aggregation; ldmatrix frags; MMA row-sums.
// Ts buffers have 264 "n-rows": 0..255 = T cols, 256 = ones (row sums),
// 257..263 = zeros. cs==3 warps compute the extra ones-block.
// ============================================================
#define TS_SZ   (264 * PB2)                  // 19008 halfs per buffer
#define PS_SZ   (128 * PB2)                  // 9216 halfs per buffer
#define DS_WOFF ((2 * TS_SZ + 2 * PS_SZ) / 2)  // u32 offset 28224 (byte 112896)
#define SMEM_DYN (112896 + 1536 + 256)

__global__ void __launch_bounds__(512, 1) k_aggregate(const int* __restrict__ adj,
                                                      float* __restrict__ out) {
    extern __shared__ __align__(16) __half dyn[];
    uint32_t* dS = (uint32_t*)dyn + DS_WOFF;   // [slot][head][arr][32] u32
    __shared__ float lsm[2][BM];

    const int t = threadIdx.x;
    const int i0 = blockIdx.x * BM;
    const int lane = t & 31, warp = t >> 5;
    const int q = lane >> 2, cl = lane & 3;
    const int l7 = lane & 7, lg = lane >> 3;

    // mma roles
    const int rg = warp & 1;
    const int h  = (warp >> 1) & 1;
    const int cs = warp >> 2;

    // builder role
    const int br = t >> 3, bjq = t & 7;

    const int* arow = adj + (size_t)(i0 + br) * NN;

    // src factor packs (both heads)
    uint4 su[2];
    su[0] = g_hSRC4[(i0 + br) * 2 + 0];
    su[1] = g_hSRC4[(i0 + br) * 2 + 1];

    // ---- prologue prefetch ----
    uint4 Tpre[4];
#pragma unroll
    for (int p = 0; p < 4; p++)
        Tpre[p] = *(const uint4*)(g_Thb + (size_t)(t + p * 512) * 8);
    int4 acur[2];
    acur[0] = *(const int4*)(arow + 4 * bjq);
    acur[1] = *(const int4*)(arow + 4 * (bjq + 8));

    // dS stage role (t<192): [head][arr][w]
    const int sh2 = t / 96, sar = (t % 96) / 32, sw = t % 32;
    const uint32_t* gDp = g_hD + (sh2 * 3 + sar) * 4096;
    uint32_t dpre = 0;
    if (t < 192) {
        dS[((0 * 2 + sh2) * 3 + sar) * 32 + sw] = gDp[sw];   // tile 0 -> slot 0
        dpre = gDp[32 + sw];                                  // tile 1
    }

    // ones rows (256..263) in both Ts buffers
    if (t < 256) {
        int buf = t >> 7, rr = 256 + ((t >> 4) & 7), seg = t & 15;
        __half2 v = (rr == 256) ? __floats2half2_rn(1.f, 1.f)
                                : __floats2half2_rn(0.f, 0.f);
        uint32_t u = *(uint32_t*)&v;
        *(uint2*)(dyn + buf * TS_SZ + rr * PB2 + seg * 4) = make_uint2(u, u);
    }

    float acc[2][4][4];
    float accl[2][4];
#pragma unroll
    for (int mf = 0; mf < 2; mf++) {
#pragma unroll
        for (int nb = 0; nb < 4; nb++)
#pragma unroll
            for (int c = 0; c < 4; c++) acc[mf][nb][c] = 0.f;
#pragma unroll
        for (int c = 0; c < 4; c++) accl[mf][c] = 0.f;
    }

    __syncthreads();

    for (int tile = 0; tile < NT2; ++tile) {
        const int s = tile & 1;
        __half* Ts = dyn + s * TS_SZ;
        __half* Ps = dyn + 2 * TS_SZ + s * PS_SZ;

        // ---- publish T tile from prefetch regs ----
#pragma unroll
        for (int p = 0; p < 4; p++) {
            int chunk = t + p * 512;
            int c = chunk >> 3, kc = chunk & 7;
            *(uint4*)(Ts + c * PB2 + kc * 8) = Tpre[p];
        }
        if (tile + 1 < NT2) {
            const __half* src = g_Thb + (size_t)(tile + 1) * 16384;
#pragma unroll
            for (int p = 0; p < 4; p++)
                Tpre[p] = *(const uint4*)(src + (size_t)(t + p * 512) * 8);
        }
        // stage dst factors for tile+1, prefetch tile+2
        if (t < 192 && tile + 1 < NT2) {
            dS[((((tile + 1) & 1) * 2 + sh2) * 3 + sar) * 32 + sw] = dpre;
            if (tile + 2 < NT2) dpre = gDp[(tile + 2) * 32 + sw];
        }

        // ---- build P (half2 separable exp) -> Ps ----
#pragma unroll
        for (int hh = 0; hh < 2; hh++) {
            const __half2 S2   = u2h(su[hh].x);
            const __half2 sEmF = u2h(su[hh].y);
            const __half2 sF   = u2h(su[hh].z);
            const uint32_t* db = dS + (s * 2 + hh) * 3 * 32;
            const __half2 zero = __floats2half2_rn(0.f, 0.f);
#pragma unroll
            for (int g = 0; g < 2; g++) {
                const int j4 = bjq + 8 * g;
                uint2 Du = *(const uint2*)(db + 2 * j4);
                uint2 Eu = *(const uint2*)(db + 32 + 2 * j4);
                uint2 Fu = *(const uint2*)(db + 64 + 2 * j4);
                const int* av = (const int*)&acur[g];
                uint32_t outp[2];
#pragma unroll
                for (int pp = 0; pp < 2; pp++) {
                    uint32_t Dw = pp ? Du.y : Du.x;
                    uint32_t Ew = pp ? Eu.y : Eu.x;
                    uint32_t Fw = pp ? Fu.y : Fu.x;
                    __half2 cc = __hadd2(S2, u2h(Dw));
                    __half2 m  = __hge2(cc, zero);
                    __half2 fs = __hfma2(m, sEmF, sF);
                    __half2 fd = __hfma2(m, u2h(Ew), u2h(Fw));
                    __half2 am = __floats2half2_rn(av[2 * pp] > 0 ? 1.f : 0.f,
                                                   av[2 * pp + 1] > 0 ? 1.f : 0.f);
                    __half2 v = __hmul2(__hmul2(fs, fd), am);
                    outp[pp] = *(uint32_t*)&v;
                }
                *(uint2*)(Ps + (hh * 64 + br) * PB2 + 4 * j4) = make_uint2(outp[0], outp[1]);
            }
        }
        // prefetch next adjacency
        if (tile + 1 < NT2) {
            const int jb = (tile + 1) * KT2;
            acur[0] = *(const int4*)(arow + jb + 4 * bjq);
            acur[1] = *(const int4*)(arow + jb + 4 * (bjq + 8));
        }

        __syncthreads();

        // ---- HMMA phase: ldmatrix frags + mma ----
        {
            const uint32_t ts_b = smem_u32p(Ts);
            const uint32_t ps_b = smem_u32p(Ps) + (uint32_t)(h * 64 * PB2 * 2);
#pragma unroll
            for (int kb2 = 0; kb2 < 2; kb2++) {
                uint32_t a[2][2][4];
#pragma unroll
                for (int mf = 0; mf < 2; mf++)
#pragma unroll
                    for (int ki = 0; ki < 2; ki++) {
                        int kb = kb2 * 2 + ki;
                        uint32_t addr = ps_b +
                            (uint32_t)(((32 * rg + 16 * mf + l7 + (lg & 1) * 8) * PB2 +
                                        kb * 16 + (lg >> 1) * 8) * 2);
                        ldsm4(a[mf][ki], addr);
                    }
#pragma unroll
                for (int nb = 0; nb < 4; nb++) {
                    int ncol = h * FDIM + cs * 32 + nb * 8;
                    uint32_t baddr = ts_b +
                        (uint32_t)(((ncol + l7) * PB2 + kb2 * 32 + lg * 8) * 2);
                    uint32_t b[4];
                    ldsm4(b, baddr);
                    mma16816(acc[0][nb], a[0][0], b[0], b[1]);
                    mma16816(acc[0][nb], a[0][1], b[2], b[3]);
                    mma16816(acc[1][nb], a[1][0], b[0], b[1]);
                    mma16816(acc[1][nb], a[1][1], b[2], b[3]);
                }
                if (cs == 3) {   // ones-block: row sums
                    uint32_t baddr = ts_b +
                        (uint32_t)(((256 + l7) * PB2 + kb2 * 32 + lg * 8) * 2);
                    uint32_t b[4];
                    ldsm4(b, baddr);
                    mma16816(accl[0], a[0][0], b[0], b[1]);
                    mma16816(accl[0], a[0][1], b[2], b[3]);
                    mma16816(accl[1], a[1][0], b[0], b[1]);
                    mma16816(accl[1], a[1][1], b[2], b[3]);
                }
            }
        }
    }

    // ---- distribute row sums ----
    if (cs == 3 && cl == 0) {
#pragma unroll
        for (int mf = 0; mf < 2; mf++) {
            lsm[h][32 * rg + 16 * mf + q]     = accl[mf][0];
            lsm[h][32 * rg + 16 * mf + q + 8] = accl[mf][2];
        }
    }
    __syncthreads();

    // ---- epilogue: normalize, head exchange via smem, head-mean, store ----
    float* ex = (float*)dyn;    // 64 x 128 fp32 (buffers dead now)
    if (h == 1) {
#pragma unroll
        for (int mf = 0; mf < 2; mf++) {
            const int rowA = 32 * rg + 16 * mf + q;
            const int rowB = rowA + 8;
            const float lA = lsm[1][rowA], lB = lsm[1][rowB];
            const float iA = (lA > 0.f) ? 1.f / lA : 0.f;
            const float iB = (lB > 0.f) ? 1.f / lB : 0.f;
#pragma unroll
            for (int nb = 0; nb < 4; nb++) {
                const int colf = cs * 32 + nb * 8 + 2 * cl;
                *(float2*)&ex[rowA * FDIM + colf] =
                    make_float2(acc[mf][nb][0] * iA, acc[mf][nb][1] * iA);
                *(float2*)&ex[rowB * FDIM + colf] =
                    make_float2(acc[mf][nb][2] * iB, acc[mf][nb][3] * iB);
            }
        }
    }
    __syncthreads();
    if (h == 0) {
#pragma unroll
        for (int mf = 0; mf < 2; mf++) {
            const int rowA = 32 * rg + 16 * mf + q;
            const int rowB = rowA + 8;
            const float lA = lsm[0][rowA], lB = lsm[0][rowB];
            const float iA = (lA > 0.f) ? 1.f / lA : 0.f;
            const float iB = (lB > 0.f) ? 1.f / lB : 0.f;
#pragma unroll
            for (int nb = 0; nb < 4; nb++) {
                const int colf = cs * 32 + nb * 8 + 2 * cl;
                float2 e0 = *(const float2*)&ex[rowA * FDIM + colf];
                float2 e1 = *(const float2*)&ex[rowB * FDIM + colf];
                float2 oA = make_float2(0.5f * (acc[mf][nb][0] * iA + e0.x),
                                        0.5f * (acc[mf][nb][1] * iA + e0.y));
                float2 oB = make_float2(0.5f * (acc[mf][nb][2] * iB + e1.x),
                                        0.5f * (acc[mf][nb][3] * iB + e1.y));
                *(float2*)&out[(size_t)(i0 + rowA) * FDIM + colf] = oA;
                *(float2*)&out[(size_t)(i0 + rowB) * FDIM + colf] = oB;
            }
        }
    }
}

// ============================================================
extern "C" void kernel_launch(void* const* d_in, const int* in_sizes, int n_in,
                              void* d_out, int out_size) {
    const float* feat = (const float*)d_in[0];
    const int*   adj  = (const int*)d_in[1];
    const float* W    = (const float*)d_in[2];
    const float* asrc = (const float*)d_in[3];
    const float* adst = (const float*)d_in[4];
    float* out = (float*)d_out;

    cudaFuncSetAttribute(k_aggregate, cudaFuncAttributeMaxDynamicSharedMemorySize, SMEM_DYN);

    dim3 g1(NN / 64, CDIM / 64);
    k_transform<<<g1, 256>>>(feat, W);
    k_scores<<<NN / 8, 256>>>(asrc, adst);
    k_aggregate<<<NN / BM, 512, SMEM_DYN>>>(adj, out);
}

// round 12
// speedup vs baseline: 6.4045x; 1.1671x over previous
#include <cuda_runtime.h>
#include <cuda_fp16.h>
#include <cstdint>
#include <math.h>

#define NN    8192
#define KDIM  256
#define CDIM  256
#define FDIM  128
#define KT2   64          // dst-tile width
#define BM    64          // src rows per CTA
#define NT2   (NN / KT2)  // 128 tiles
#define PB2   72          // smem pitch in halfs (36 words == 4 mod 32 -> conflict-free)

// ---- scratch (device globals) ----
__device__ float    g_T  [NN * CDIM];     // transformed [i][h*128+f] fp32 (for k_scores)
__device__ __half   g_Thb[NN * CDIM];     // blocked fp16: [j/64][c(256)][j%64]
__device__ uint4    g_hSRC4[NN * 2];      // per (node,head): {S2, (Es-Fs)2, Fs2, 0} half2
__device__ uint32_t g_hD[2 * 3 * (NN / 2)]; // dst halves [head][arr:D,EmF,F][NN] u32 pairs

__device__ __forceinline__ __half2 u2h(uint32_t u) { return *(__half2*)&u; }

// fp16 m16n8k16 HMMA (portable PTX, sm_80+)
__device__ __forceinline__ void mma16816(float c[4], const uint32_t a[4],
                                         uint32_t b0, uint32_t b1) {
    asm volatile(
        "mma.sync.aligned.m16n8k16.row.col.f32.f16.f16.f32 "
        "{%0,%1,%2,%3}, {%4,%5,%6,%7}, {%8,%9}, {%0,%1,%2,%3};\n"
        : "+f"(c[0]), "+f"(c[1]), "+f"(c[2]), "+f"(c[3])
        : "r"(a[0]), "r"(a[1]), "r"(a[2]), "r"(a[3]), "r"(b0), "r"(b1));
}
__device__ __forceinline__ void ldsm4(uint32_t r[4], uint32_t addr) {
    asm volatile("ldmatrix.sync.aligned.m8n8.x4.shared.b16 {%0,%1,%2,%3}, [%4];"
                 : "=r"(r[0]), "=r"(r[1]), "=r"(r[2]), "=r"(r[3]) : "r"(addr));
}
__device__ __forceinline__ uint32_t smem_u32p(const void* p) {
    return (uint32_t)__cvta_generic_to_shared(p);
}
__device__ __forceinline__ void cpa16(uint32_t d, const void* s) {
    asm volatile("cp.async.cg.shared.global [%0], [%1], 16;" :: "r"(d), "l"(s));
}
#define CPA_COMMIT() asm volatile("cp.async.commit_group;" ::: "memory")
#define CPA_WAIT0()  asm volatile("cp.async.wait_group 0;" ::: "memory")

// ============================================================
// Kernel 1: T = features @ W^T via fp16 HMMA (fp32 accumulate).
// CTA = 128 rows x 64 cols, 256 threads (8 warps: 4 rowgrp x 2 colgrp),
// K chunks of 64. Writes g_T (fp32) + g_Thb (fp16 blocked).
// ============================================================
__global__ void __launch_bounds__(256) k_transform(const float* __restrict__ feat,
                                                   const float* __restrict__ W) {
    __shared__ __half Fs[128 * PB2];
    __shared__ __half Ws[64 * PB2];
    const int i0 = blockIdx.x * 128;
    const int c0 = blockIdx.y * 64;
    const int t = threadIdx.x, lane = t & 31, warp = t >> 5;
    const int rg = warp & 3, cb = warp >> 2;
    const int q = lane >> 2, cl = lane & 3, l7 = lane & 7, lg = lane >> 3;

    float acc[2][4][4];
#pragma unroll
    for (int mf = 0; mf < 2; mf++)
#pragma unroll
        for (int nb = 0; nb < 4; nb++)
#pragma unroll
            for (int c = 0; c < 4; c++) acc[mf][nb][c] = 0.f;

    // prefetch chunk 0
    float4 Fpre[8], Wpre[4];
#pragma unroll
    for (int p = 0; p < 8; p++) {
        int fi = t + p * 256;
        Fpre[p] = *(const float4*)&feat[(size_t)(i0 + (fi >> 4)) * KDIM + (fi & 15) * 4];
    }
#pragma unroll
    for (int p = 0; p < 4; p++) {
        int wi = t + p * 256;
        Wpre[p] = *(const float4*)&W[(size_t)(c0 + (wi >> 4)) * KDIM + (wi & 15) * 4];
    }

    const uint32_t fs_b = smem_u32p(Fs);
    const uint32_t ws_b = smem_u32p(Ws);

    for (int kc = 0; kc < 4; kc++) {
        // stage current chunk (fp32 -> fp16)
#pragma unroll
        for (int p = 0; p < 8; p++) {
            int fi = t + p * 256;
            __half2 h0 = __floats2half2_rn(Fpre[p].x, Fpre[p].y);
            __half2 h1 = __floats2half2_rn(Fpre[p].z, Fpre[p].w);
            *(uint2*)&Fs[(fi >> 4) * PB2 + (fi & 15) * 4] =
                make_uint2(*(uint32_t*)&h0, *(uint32_t*)&h1);
        }
#pragma unroll
        for (int p = 0; p < 4; p++) {
            int wi = t + p * 256;
            __half2 h0 = __floats2half2_rn(Wpre[p].x, Wpre[p].y);
            __half2 h1 = __floats2half2_rn(Wpre[p].z, Wpre[p].w);
            *(uint2*)&Ws[(wi >> 4) * PB2 + (wi & 15) * 4] =
                make_uint2(*(uint32_t*)&h0, *(uint32_t*)&h1);
        }
        // prefetch next chunk
        if (kc + 1 < 4) {
            const int ko = (kc + 1) * 64;
#pragma unroll
            for (int p = 0; p < 8; p++) {
                int fi = t + p * 256;
                Fpre[p] = *(const float4*)&feat[(size_t)(i0 + (fi >> 4)) * KDIM + ko + (fi & 15) * 4];
            }
#pragma unroll
            for (int p = 0; p < 4; p++) {
                int wi = t + p * 256;
                Wpre[p] = *(const float4*)&W[(size_t)(c0 + (wi >> 4)) * KDIM + ko + (wi & 15) * 4];
            }
        }
        __syncthreads();

        // mma on this chunk (k = 64)
#pragma unroll
        for (int kb2 = 0; kb2 < 2; kb2++) {
            uint32_t a[2][2][4];
#pragma unroll
            for (int mf = 0; mf < 2; mf++)
#pragma unroll
                for (int ki = 0; ki < 2; ki++) {
                    int kb = kb2 * 2 + ki;
                    uint32_t addr = fs_b +
                        (uint32_t)(((32 * rg + 16 * mf + l7 + (lg & 1) * 8) * PB2 +
                                    kb * 16 + (lg >> 1) * 8) * 2);
                    ldsm4(a[mf][ki], addr);
                }
#pragma unroll
            for (int nb = 0; nb < 4; nb++) {
                uint32_t baddr = ws_b +
                    (uint32_t)(((32 * cb + 8 * nb + l7) * PB2 + kb2 * 32 + lg * 8) * 2);
                uint32_t b[4];
                ldsm4(b, baddr);
                mma16816(acc[0][nb], a[0][0], b[0], b[1]);
                mma16816(acc[0][nb], a[0][1], b[2], b[3]);
                mma16816(acc[1][nb], a[1][0], b[0], b[1]);
                mma16816(acc[1][nb], a[1][1], b[2], b[3]);
            }
        }
        __syncthreads();
    }

    // epilogue: g_T fp32 + g_Thb fp16 blocked
#pragma unroll
    for (int mf = 0; mf < 2; mf++)
#pragma unroll
        for (int nb = 0; nb < 4; nb++) {
            const int row0 = 32 * rg + 16 * mf + q;
            const int row1 = row0 + 8;
            const int colg = c0 + 32 * cb + 8 * nb + 2 * cl;
            *(float2*)&g_T[(size_t)(i0 + row0) * CDIM + colg] =
                make_float2(acc[mf][nb][0], acc[mf][nb][1]);
            *(float2*)&g_T[(size_t)(i0 + row1) * CDIM + colg] =
                make_float2(acc[mf][nb][2], acc[mf][nb][3]);
#pragma unroll
            for (int c4 = 0; c4 < 4; c4++) {
                const int row = (c4 < 2) ? row0 : row1;
                const int cg = colg + (c4 & 1);
                g_Thb[(size_t)((i0 + row) >> 6) * 16384 + cg * 64 + (row & 63)] =
                    __float2half_rn(acc[mf][nb][c4]);
            }
        }
}

// ============================================================
// Kernel 2: scores + packed half2 separable-exp factors
// ============================================================
__global__ void __launch_bounds__(256) k_scores(const float* __restrict__ attn_src,
                                                const float* __restrict__ attn_dst) {
    __shared__ float as_[CDIM], ad_[CDIM];
    int t = threadIdx.x;
    as_[t] = attn_src[t];
    ad_[t] = attn_dst[t];
    __syncthreads();
    int warp = t >> 5, lane = t & 31;
    int row = blockIdx.x * 8 + warp;

    float s0 = 0.f, s1 = 0.f, d0 = 0.f, d1 = 0.f;
#pragma unroll
    for (int f = lane; f < FDIM; f += 32) {
        float t0 = g_T[(size_t)row * CDIM + f];
        float t1 = g_T[(size_t)row * CDIM + FDIM + f];
        s0 = fmaf(t0, as_[f], s0);
        d0 = fmaf(t0, ad_[f], d0);
        s1 = fmaf(t1, as_[FDIM + f], s1);
        d1 = fmaf(t1, ad_[FDIM + f], d1);
    }
#pragma unroll
    for (int o = 16; o > 0; o >>= 1) {
        s0 += __shfl_xor_sync(0xFFFFFFFFu, s0, o);
        s1 += __shfl_xor_sync(0xFFFFFFFFu, s1, o);
        d0 += __shfl_xor_sync(0xFFFFFFFFu, d0, o);
        d1 += __shfl_xor_sync(0xFFFFFFFFu, d1, o);
    }
    if (lane == 0) {
        float Ss[2] = {s0, s1}, Dd[2] = {d0, d1};
        __half* hb = (__half*)g_hD;
#pragma unroll
        for (int h = 0; h < 2; h++) {
            float S = Ss[h], D = Dd[h];
            float Es = expf(S), Fs = expf(0.2f * S);
            float Ed = expf(D), Fd = expf(0.2f * D);
            __half2 a = __floats2half2_rn(S, S);
            __half2 b = __floats2half2_rn(Es - Fs, Es - Fs);
            __half2 c = __floats2half2_rn(Fs, Fs);
            uint4 u;
            u.x = *(uint32_t*)&a; u.y = *(uint32_t*)&b; u.z = *(uint32_t*)&c; u.w = 0;
            g_hSRC4[row * 2 + h] = u;
            hb[(h * 3 + 0) * NN + row] = __float2half_rn(D);
            hb[(h * 3 + 1) * NN + row] = __float2half_rn(Ed - Fd);
            hb[(h * 3 + 2) * NN + row] = __float2half_rn(Fd);
        }
    }
}

// ============================================================
// Kernel 3: fp16 m16n8k16 aggregation; cp.async T-tiles; MMA row-sums.
// ============================================================
#define TS_SZ   (264 * PB2)                  // 19008 halfs per buffer
#define PS_SZ   (128 * PB2)                  // 9216 halfs per buffer
#define DS_WOFF ((2 * TS_SZ + 2 * PS_SZ) / 2)  // u32 offset (byte 112896)
#define SMEM_DYN (112896 + 1536 + 256)

__global__ void __launch_bounds__(512, 1) k_aggregate(const int* __restrict__ adj,
                                                      float* __restrict__ out) {
    extern __shared__ __align__(16) __half dyn[];
    uint32_t* dS = (uint32_t*)dyn + DS_WOFF;   // [slot][head][arr][32] u32
    __shared__ float lsm[2][BM];

    const int t = threadIdx.x;
    const int i0 = blockIdx.x * BM;
    const int lane = t & 31, warp = t >> 5;
    const int q = lane >> 2, cl = lane & 3;
    const int l7 = lane & 7, lg = lane >> 3;

    // mma roles
    const int rg = warp & 1;
    const int h  = (warp >> 1) & 1;
    const int cs = warp >> 2;

    // builder role
    const int br = t >> 3, bjq = t & 7;

    const int* arow = adj + (size_t)(i0 + br) * NN;

    uint4 su[2];
    su[0] = g_hSRC4[(i0 + br) * 2 + 0];
    su[1] = g_hSRC4[(i0 + br) * 2 + 1];

    // ---- prologue: issue cp.async for tile 0 -> buffer 0 ----
    {
        const uint32_t dstb = smem_u32p(dyn);
#pragma unroll
        for (int p = 0; p < 4; p++) {
            int chunk = t + p * 512;
            int c = chunk >> 3, kc = chunk & 7;
            cpa16(dstb + (uint32_t)((c * PB2 + kc * 8) * 2), g_Thb + (size_t)chunk * 8);
        }
        CPA_COMMIT();
    }
    int4 acur[2];
    acur[0] = *(const int4*)(arow + 4 * bjq);
    acur[1] = *(const int4*)(arow + 4 * (bjq + 8));

    // dS stage role (t<192): [head][arr][w]
    const int sh2 = t / 96, sar = (t % 96) / 32, sw = t % 32;
    const uint32_t* gDp = g_hD + (sh2 * 3 + sar) * 4096;
    uint32_t dpre = 0;
    if (t < 192) {
        dS[((0 * 2 + sh2) * 3 + sar) * 32 + sw] = gDp[sw];
        dpre = gDp[32 + sw];
    }

    // ones rows (256..263) in both Ts buffers
    if (t < 256) {
        int buf = t >> 7, rr = 256 + ((t >> 4) & 7), seg = t & 15;
        __half2 v = (rr == 256) ? __floats2half2_rn(1.f, 1.f)
                                : __floats2half2_rn(0.f, 0.f);
        uint32_t u = *(uint32_t*)&v;
        *(uint2*)(dyn + buf * TS_SZ + rr * PB2 + seg * 4) = make_uint2(u, u);
    }

    float acc[2][4][4];
    float accl[2][4];
#pragma unroll
    for (int mf = 0; mf < 2; mf++) {
#pragma unroll
        for (int nb = 0; nb < 4; nb++)
#pragma unroll
            for (int c = 0; c < 4; c++) acc[mf][nb][c] = 0.f;
#pragma unroll
        for (int c = 0; c < 4; c++) accl[mf][c] = 0.f;
    }

    __syncthreads();

    for (int tile = 0; tile < NT2; ++tile) {
        const int s = tile & 1;
        __half* Ts = dyn + s * TS_SZ;
        __half* Ps = dyn + 2 * TS_SZ + s * PS_SZ;

        // stage dst factors for tile+1, prefetch tile+2
        if (t < 192 && tile + 1 < NT2) {
            dS[((((tile + 1) & 1) * 2 + sh2) * 3 + sar) * 32 + sw] = dpre;
            if (tile + 2 < NT2) dpre = gDp[(tile + 2) * 32 + sw];
        }

        // ---- build P (half2 separable exp) -> Ps ----
#pragma unroll
        for (int hh = 0; hh < 2; hh++) {
            const __half2 S2   = u2h(su[hh].x);
            const __half2 sEmF = u2h(su[hh].y);
            const __half2 sF   = u2h(su[hh].z);
            const uint32_t* db = dS + (s * 2 + hh) * 3 * 32;
            const __half2 zero = __floats2half2_rn(0.f, 0.f);
#pragma unroll
            for (int g = 0; g < 2; g++) {
                const int j4 = bjq + 8 * g;
                uint2 Du = *(const uint2*)(db + 2 * j4);
                uint2 Eu = *(const uint2*)(db + 32 + 2 * j4);
                uint2 Fu = *(const uint2*)(db + 64 + 2 * j4);
                const int* av = (const int*)&acur[g];
                uint32_t outp[2];
#pragma unroll
                for (int pp = 0; pp < 2; pp++) {
                    uint32_t Dw = pp ? Du.y : Du.x;
                    uint32_t Ew = pp ? Eu.y : Eu.x;
                    uint32_t Fw = pp ? Fu.y : Fu.x;
                    __half2 cc = __hadd2(S2, u2h(Dw));
                    __half2 m  = __hge2(cc, zero);
                    __half2 fs = __hfma2(m, sEmF, sF);
                    __half2 fd = __hfma2(m, u2h(Ew), u2h(Fw));
                    __half2 am = __floats2half2_rn(av[2 * pp] > 0 ? 1.f : 0.f,
                                                   av[2 * pp + 1] > 0 ? 1.f : 0.f);
                    __half2 v = __hmul2(__hmul2(fs, fd), am);
                    outp[pp] = *(uint32_t*)&v;
                }
                *(uint2*)(Ps + (hh * 64 + br) * PB2 + 4 * j4) = make_uint2(outp[0], outp[1]);
            }
        }
        // prefetch next adjacency
        if (tile + 1 < NT2) {
            const int jb = (tile + 1) * KT2;
            acur[0] = *(const int4*)(arow + jb + 4 * bjq);
            acur[1] = *(const int4*)(arow + jb + 4 * (bjq + 8));
        }

        CPA_WAIT0();          // Ts(s) for tile t complete
        __syncthreads();      // all threads see Ts(s) + Ps(s); R(t-1) fully done

        // issue cp.async for tile+1 into the other buffer (overlaps mma below)
        if (tile + 1 < NT2) {
            const uint32_t dstb = smem_u32p(dyn + (s ^ 1) * TS_SZ);
            const __half* src = g_Thb + (size_t)(tile + 1) * 16384;
#pragma unroll
            for (int p = 0; p < 4; p++) {
                int chunk = t + p * 512;
                int c = chunk >> 3, kc = chunk & 7;
                cpa16(dstb + (uint32_t)((c * PB2 + kc * 8) * 2), src + (size_t)chunk * 8);
            }
            CPA_COMMIT();
        }

        // ---- HMMA phase ----
        {
            const uint32_t ts_b = smem_u32p(Ts);
            const uint32_t ps_b = smem_u32p(Ps) + (uint32_t)(h * 64 * PB2 * 2);
#pragma unroll
            for (int kb2 = 0; kb2 < 2; kb2++) {
                uint32_t a[2][2][4];
#pragma unroll
                for (int mf = 0; mf < 2; mf++)
#pragma unroll
                    for (int ki = 0; ki < 2; ki++) {
                        int kb = kb2 * 2 + ki;
                        uint32_t addr = ps_b +
                            (uint32_t)(((32 * rg + 16 * mf + l7 + (lg & 1) * 8) * PB2 +
                                        kb * 16 + (lg >> 1) * 8) * 2);
                        ldsm4(a[mf][ki], addr);
                    }
#pragma unroll
                for (int nb = 0; nb < 4; nb++) {
                    int ncol = h * FDIM + cs * 32 + nb * 8;
                    uint32_t baddr = ts_b +
                        (uint32_t)(((ncol + l7) * PB2 + kb2 * 32 + lg * 8) * 2);
                    uint32_t b[4];
                    ldsm4(b, baddr);
                    mma16816(acc[0][nb], a[0][0], b[0], b[1]);
                    mma16816(acc[0][nb], a[0][1], b[2], b[3]);
                    mma16816(acc[1][nb], a[1][0], b[0], b[1]);
                    mma16816(acc[1][nb], a[1][1], b[2], b[3]);
                }
                if (cs == 3) {   // ones-block: row sums
                    uint32_t baddr = ts_b +
                        (uint32_t)(((256 + l7) * PB2 + kb2 * 32 + lg * 8) * 2);
                    uint32_t b[4];
                    ldsm4(b, baddr);
                    mma16816(accl[0], a[0][0], b[0], b[1]);
                    mma16816(accl[0], a[0][1], b[2], b[3]);
                    mma16816(accl[1], a[1][0], b[0], b[1]);
                    mma16816(accl[1], a[1][1], b[2], b[3]);
                }
            }
        }
    }

    // ---- distribute row sums ----
    if (cs == 3 && cl == 0) {
#pragma unroll
        for (int mf = 0; mf < 2; mf++) {
            lsm[h][32 * rg + 16 * mf + q]     = accl[mf][0];
            lsm[h][32 * rg + 16 * mf + q + 8] = accl[mf][2];
        }
    }
    __syncthreads();

    // ---- epilogue ----
    float* ex = (float*)dyn;
    if (h == 1) {
#pragma unroll
        for (int mf = 0; mf < 2; mf++) {
            const int rowA = 32 * rg + 16 * mf + q;
            const int rowB = rowA + 8;
            const float lA = lsm[1][rowA], lB = lsm[1][rowB];
            const float iA = (lA > 0.f) ? 1.f / lA : 0.f;
            const float iB = (lB > 0.f) ? 1.f / lB : 0.f;
#pragma unroll
            for (int nb = 0; nb < 4; nb++) {
                const int colf = cs * 32 + nb * 8 + 2 * cl;
                *(float2*)&ex[rowA * FDIM + colf] =
                    make_float2(acc[mf][nb][0] * iA, acc[mf][nb][1] * iA);
                *(float2*)&ex[rowB * FDIM + colf] =
                    make_float2(acc[mf][nb][2] * iB, acc[mf][nb][3] * iB);
            }
        }
    }
    __syncthreads();
    if (h == 0) {
#pragma unroll
        for (int mf = 0; mf < 2; mf++) {
            const int rowA = 32 * rg + 16 * mf + q;
            const int rowB = rowA + 8;
            const float lA = lsm[0][rowA], lB = lsm[0][rowB];
            const float iA = (lA > 0.f) ? 1.f / lA : 0.f;
            const float iB = (lB > 0.f) ? 1.f / lB : 0.f;
#pragma unroll
            for (int nb = 0; nb < 4; nb++) {
                const int colf = cs * 32 + nb * 8 + 2 * cl;
                float2 e0 = *(const float2*)&ex[rowA * FDIM + colf];
                float2 e1 = *(const float2*)&ex[rowB * FDIM + colf];
                float2 oA = make_float2(0.5f * (acc[mf][nb][0] * iA + e0.x),
                                        0.5f * (acc[mf][nb][1] * iA + e0.y));
                float2 oB = make_float2(0.5f * (acc[mf][nb][2] * iB + e1.x),
                                        0.5f * (acc[mf][nb][3] * iB + e1.y));
                *(float2*)&out[(size_t)(i0 + rowA) * FDIM + colf] = oA;
                *(float2*)&out[(size_t)(i0 + rowB) * FDIM + colf] = oB;
            }
        }
    }
}

// ============================================================
extern "C" void kernel_launch(void* const* d_in, const int* in_sizes, int n_in,
                              void* d_out, int out_size) {
    const float* feat = (const float*)d_in[0];
    const int*   adj  = (const int*)d_in[1];
    const float* W    = (const float*)d_in[2];
    const float* asrc = (const float*)d_in[3];
    const float* adst = (const float*)d_in[4];
    float* out = (float*)d_out;

    cudaFuncSetAttribute(k_aggregate, cudaFuncAttributeMaxDynamicSharedMemorySize, SMEM_DYN);

    dim3 g1(NN / 128, CDIM / 64);
    k_transform<<<g1, 256>>>(feat, W);
    k_scores<<<NN / 8, 256>>>(asrc, adst);
    k_aggregate<<<NN / BM, 512, SMEM_DYN>>>(adj, out);
}